// round 8
// baseline (speedup 1.0000x reference)
#include <cuda_runtime.h>
#include <math.h>
#include <stdint.h>

#define B_ 1024
#define D_ 1024
#define H_ 4096
#define C_ 5120
#define LN_EPS 1e-3f
#define KSLICE_D 4

// ---------------- scratch (device globals: allocation-free) ----------------
// int8 limbs
__device__ __align__(1024) int8_t g_wu1[(long)H_ * C_], g_wu2[(long)H_ * C_];
__device__ __align__(1024) int8_t g_wr1[(long)H_ * C_], g_wr2[(long)H_ * C_];
__device__ __align__(1024) int8_t g_wg1[(long)H_ * C_], g_wg2[(long)H_ * C_];
__device__ __align__(1024) int8_t g_wp1[(long)H_ * C_], g_wp2[(long)H_ * C_];
__device__ __align__(1024) int8_t g_wd1[(long)D_ * H_], g_wd2[(long)D_ * H_];
__device__ __align__(1024) int8_t g_xa1[B_ * C_], g_xa2[B_ * C_];
__device__ __align__(1024) int8_t g_ya1[B_ * C_], g_ya2[B_ * C_];
__device__ __align__(1024) int8_t g_za1[B_ * H_], g_za2[B_ * H_];
// scales
__device__ float g_sa1[B_], g_sa2[B_], g_sa3[B_];
__device__ float g_sbu[H_], g_sbr[H_], g_sbg[H_], g_sbp[H_], g_sbd[D_];
// fp32 intermediates
__device__ float g_u [B_ * H_];
__device__ float g_rh[B_ * H_];
__device__ float g_g [B_ * H_];
__device__ float g_up[B_ * H_];
__device__ float g_nh[B_ * H_];
__device__ float g_do[KSLICE_D * B_ * D_];

// ---------------- helpers ----------------
__device__ __forceinline__ uint32_t smem_u32(const void* p) {
    uint32_t a;
    asm("{ .reg .u64 t; cvta.to.shared.u64 t, %1; cvt.u32.u64 %0, t; }" : "=r"(a) : "l"(p));
    return a;
}
__device__ __forceinline__ void cp16(uint32_t dst, const void* src) {
    asm volatile("cp.async.cg.shared.global [%0], [%1], 16;" :: "r"(dst), "l"(src) : "memory");
}
__device__ __forceinline__ void ldsm_x4(uint32_t* r, uint32_t addr) {
    asm volatile("ldmatrix.sync.aligned.m8n8.x4.shared.b16 {%0,%1,%2,%3}, [%4];"
                 : "=r"(r[0]), "=r"(r[1]), "=r"(r[2]), "=r"(r[3]) : "r"(addr));
}
__device__ __forceinline__ void imma(int* c, const uint32_t* a, uint32_t b0, uint32_t b1) {
    asm volatile(
        "mma.sync.aligned.m16n8k32.row.col.s32.s8.s8.s32 "
        "{%0,%1,%2,%3}, {%4,%5,%6,%7}, {%8,%9}, {%0,%1,%2,%3};"
        : "+r"(c[0]), "+r"(c[1]), "+r"(c[2]), "+r"(c[3])
        : "r"(a[0]), "r"(a[1]), "r"(a[2]), "r"(a[3]), "r"(b0), "r"(b1));
}
__device__ __forceinline__ float sigm(float x) { return 1.0f / (1.0f + expf(-x)); }

__device__ __forceinline__ uint32_t pack_q1(float4 f, float inv, uint32_t& q2u) {
    float q[4] = {f.x * inv, f.y * inv, f.z * inv, f.w * inv};
    int i1[4], i2[4];
#pragma unroll
    for (int e = 0; e < 4; e++) {
        float q1 = rintf(q[e]);
        q1 = fminf(fmaxf(q1, -127.f), 127.f);
        float q2 = rintf((q[e] - q1) * 256.f);
        q2 = fminf(fmaxf(q2, -127.f), 127.f);
        i1[e] = (int)q1; i2[e] = (int)q2;
    }
    uint32_t u1 = (uint32_t)(uint8_t)(int8_t)i1[0] | ((uint32_t)(uint8_t)(int8_t)i1[1] << 8)
                | ((uint32_t)(uint8_t)(int8_t)i1[2] << 16) | ((uint32_t)(uint8_t)(int8_t)i1[3] << 24);
    q2u = (uint32_t)(uint8_t)(int8_t)i2[0] | ((uint32_t)(uint8_t)(int8_t)i2[1] << 8)
        | ((uint32_t)(uint8_t)(int8_t)i2[2] << 16) | ((uint32_t)(uint8_t)(int8_t)i2[3] << 24);
    return u1;
}

// ---------------- int8 IMMA GEMM (1 CTA/SM) ----------------
// Stage: KT=64 int8. Layout per tensor: 4 planes of [128 rows][16B] (2KB each = 8KB/tensor).
// Stage = A1(0) A2(8192) B1(16384) B2(24576) = 32KB. 3 stages = 96KB.
#define KT 64
#define STG 3
#define STAGE_BYTES 32768u

// MODE 0: nt<nhalf -> u=sigmoid(v+b0); else rh=sigmoid(v+b1)*hmul -> fp32 rhout
// MODE 1: raw v+bias -> fout0 / fout1
// MODE 2: raw v (no bias) -> fout0 + z*B_*D_
template<int MODE>
__global__ void __launch_bounds__(256, 1) gemm_imma(
    const int8_t* __restrict__ A1, const int8_t* __restrict__ A2,
    const float* __restrict__ sA, int ldA,
    const int8_t* __restrict__ B0a, const int8_t* __restrict__ B0b, const float* __restrict__ sB0,
    const int8_t* __restrict__ B1a, const int8_t* __restrict__ B1b, const float* __restrict__ sB1,
    int ldB,
    const float* __restrict__ bias0, const float* __restrict__ bias1,
    const float* __restrict__ hmul,
    float* __restrict__ fout0, float* __restrict__ fout1, float* __restrict__ rhout,
    int K, int nhalf, int kslices)
{
    extern __shared__ __align__(1024) char smraw[];
    const uint32_t sb = smem_u32(smraw);

    const int tid = threadIdx.x, lane = tid & 31, wid = tid >> 5;
    const int wm = (wid >> 2) * 64;
    const int wn = (wid & 3) * 32;
    const int nt = blockIdx.x, mt = blockIdx.y;
    const bool second = nt >= nhalf;
    const int ntin = second ? nt - nhalf : nt;
    const int8_t* Ba = second ? B1a : B0a;
    const int8_t* Bb = second ? B1b : B0b;
    const float* sB  = second ? sB1 : sB0;
    const float* bias = second ? bias1 : bias0;

    const int m0 = mt * 128, n0 = ntin * 128;
    const int Ks = K / kslices;
    const int kbeg = blockIdx.z * Ks;
    const int S = Ks / KT;

    // loader: tid -> row = tid>>1, chunks {2*(tid&1), +1}; plane = chunk
    const int lr = tid >> 1;
    const int lh = (tid & 1) * 2;
    auto load_stage = [&](int slot, int kk) {
        const uint32_t tb = sb + (uint32_t)slot * STAGE_BYTES;
        const size_t arow = (size_t)(m0 + lr) * ldA + kk;
        const size_t brow = (size_t)(n0 + lr) * ldB + kk;
#pragma unroll
        for (int c = 0; c < 2; c++) {
            const int ch = lh + c;
            const uint32_t d = tb + (uint32_t)ch * 2048u + (uint32_t)lr * 16u;
            cp16(d,          A1 + arow + ch * 16);
            cp16(d + 8192,   A2 + arow + ch * 16);
            cp16(d + 16384,  Ba + brow + ch * 16);
            cp16(d + 24576,  Bb + brow + ch * 16);
        }
    };

    // ldmatrix lane geometry (derived from m16n8k32 fragment layout)
    const int rA = (lane & 7) + 8 * ((lane >> 3) & 1);
    const int pA = lane >> 4;            // A plane sub-select
    const int rB = (lane & 7) + 8 * (lane >> 4);
    const int pB = (lane >> 3) & 1;      // B plane sub-select
    uint32_t offA[4], offB[2];
#pragma unroll
    for (int i = 0; i < 4; i++) offA[i] = (uint32_t)(wm + i * 16 + rA) * 16u;
#pragma unroll
    for (int jp = 0; jp < 2; jp++) offB[jp] = (uint32_t)(wn + jp * 16 + rB) * 16u;

    // prologue
#pragma unroll
    for (int s = 0; s < STG - 1; s++) {
        if (s < S) load_stage(s, kbeg + s * KT);
        asm volatile("cp.async.commit_group;" ::: "memory");
    }

    int cM[4][4][4], cC[4][4][4];
#pragma unroll
    for (int i = 0; i < 4; i++)
#pragma unroll
        for (int j = 0; j < 4; j++)
#pragma unroll
            for (int e = 0; e < 4; e++) { cM[i][j][e] = 0; cC[i][j][e] = 0; }

    for (int ks = 0; ks < S; ks++) {
        asm volatile("cp.async.wait_group 1;" ::: "memory");
        __syncthreads();
        if (ks + STG - 1 < S) load_stage((ks + STG - 1) % STG, kbeg + (ks + STG - 1) * KT);
        asm volatile("cp.async.commit_group;" ::: "memory");

        const uint32_t base = sb + (uint32_t)(ks % STG) * STAGE_BYTES;
#pragma unroll
        for (int s = 0; s < 2; s++) {   // 2 k32 steps per 64-K stage
            const uint32_t pa = (uint32_t)(2 * s + pA) * 2048u;
            const uint32_t pb = (uint32_t)(2 * s + pB) * 2048u;
            uint32_t a1[4][4], b1[2][4], b2[2][4];
#pragma unroll
            for (int i = 0; i < 4; i++)   ldsm_x4(a1[i], base + pa + offA[i]);
#pragma unroll
            for (int jp = 0; jp < 2; jp++) ldsm_x4(b1[jp], base + 16384 + pb + offB[jp]);
#pragma unroll
            for (int jp = 0; jp < 2; jp++) ldsm_x4(b2[jp], base + 24576 + pb + offB[jp]);
            // main: A1*B1
#pragma unroll
            for (int i = 0; i < 4; i++)
#pragma unroll
                for (int j = 0; j < 4; j++) {
                    const int jp = j >> 1, lo = (j & 1) * 2;
                    imma(cM[i][j], a1[i], b1[jp][lo], b1[jp][lo + 1]);
                }
            // prefetch A2 under main MMAs
            uint32_t a2[4][4];
#pragma unroll
            for (int i = 0; i < 4; i++)   ldsm_x4(a2[i], base + 8192 + pa + offA[i]);
            // corr: A1*B2 + A2*B1 (shared accumulator, shared /256 scale)
#pragma unroll
            for (int i = 0; i < 4; i++)
#pragma unroll
                for (int j = 0; j < 4; j++) {
                    const int jp = j >> 1, lo = (j & 1) * 2;
                    imma(cC[i][j], a1[i], b2[jp][lo], b2[jp][lo + 1]);
                }
#pragma unroll
            for (int i = 0; i < 4; i++)
#pragma unroll
                for (int j = 0; j < 4; j++) {
                    const int jp = j >> 1, lo = (j & 1) * 2;
                    imma(cC[i][j], a2[i], b1[jp][lo], b1[jp][lo + 1]);
                }
        }
    }

    // ---- epilogue:  D = sA * (sB/127) * (main + corr/256) ----
#pragma unroll
    for (int i = 0; i < 4; i++) {
        const int rb = m0 + wm + i * 16 + (lane >> 2);
        const float sa0 = sA[rb], sa1 = sA[rb + 8];
#pragma unroll
        for (int j = 0; j < 4; j++) {
            const int gc = ntin * 128 + wn + j * 8 + 2 * (lane & 3);
            const float sc0 = sB[gc]     * (1.f / 127.f);
            const float sc1 = sB[gc + 1] * (1.f / 127.f);
#pragma unroll
            for (int half = 0; half < 2; half++) {
                const int row = rb + half * 8;
                const float sa = half ? sa1 : sa0;
                const float v0r = sa * sc0 * ((float)cM[i][j][half * 2]     + (float)cC[i][j][half * 2]     * (1.f / 256.f));
                const float v1r = sa * sc1 * ((float)cM[i][j][half * 2 + 1] + (float)cC[i][j][half * 2 + 1] * (1.f / 256.f));
                if (MODE == 0) {
                    const float v0 = v0r + bias[gc], v1 = v1r + bias[gc + 1];
                    if (!second) {
                        fout0[(long)row * H_ + gc]     = sigm(v0);
                        fout0[(long)row * H_ + gc + 1] = sigm(v1);
                    } else {
                        rhout[(long)row * H_ + gc]     = sigm(v0) * hmul[(long)row * H_ + gc];
                        rhout[(long)row * H_ + gc + 1] = sigm(v1) * hmul[(long)row * H_ + gc + 1];
                    }
                } else if (MODE == 1) {
                    float* dst = second ? fout1 : fout0;
                    dst[(long)row * H_ + gc]     = v0r + bias[gc];
                    dst[(long)row * H_ + gc + 1] = v1r + bias[gc + 1];
                } else {
                    float* dst = fout0 + (size_t)blockIdx.z * B_ * D_;
                    dst[(long)row * D_ + gc]     = v0r;
                    dst[(long)row * D_ + gc + 1] = v1r;
                }
            }
        }
    }
}

// ---------------- quantization kernels ----------------
// per-row quantize concat [xp (w1) | hp (w2)] -> int8 limbs + scale. block=256, grid=B_.
__global__ void quant_act(const float* __restrict__ xp, int w1,
                          const float* __restrict__ hp, int w2,
                          int8_t* __restrict__ q1, int8_t* __restrict__ q2,
                          float* __restrict__ sOut)
{
    const int row = blockIdx.x, tid = threadIdx.x;
    const int Cw = w1 + w2;
    const int NF = Cw / 1024;   // float4 iters per thread
    float4 f[8];
    float m = 0.f;
#pragma unroll
    for (int t = 0; t < NF; t++) {
        const int c = (t * 256 + tid) * 4;
        f[t] = (c < w1) ? *(const float4*)(xp + (size_t)row * w1 + c)
                        : *(const float4*)(hp + (size_t)row * w2 + (c - w1));
        m = fmaxf(m, fmaxf(fmaxf(fabsf(f[t].x), fabsf(f[t].y)), fmaxf(fabsf(f[t].z), fabsf(f[t].w))));
    }
    __shared__ float sm[8];
#pragma unroll
    for (int o = 16; o > 0; o >>= 1) m = fmaxf(m, __shfl_xor_sync(0xffffffffu, m, o));
    if ((tid & 31) == 0) sm[tid >> 5] = m;
    __syncthreads();
    float mx = 0.f;
#pragma unroll
    for (int w = 0; w < 8; w++) mx = fmaxf(mx, sm[w]);
    mx = fmaxf(mx, 1e-20f);
    if (tid == 0) sOut[row] = mx * (1.f / 127.f);
    const float inv = 127.f / mx;
#pragma unroll
    for (int t = 0; t < NF; t++) {
        const int c4 = t * 256 + tid;
        uint32_t u2;
        const uint32_t u1 = pack_q1(f[t], inv, u2);
        ((uint32_t*)q1)[(size_t)row * (Cw / 4) + c4] = u1;
        ((uint32_t*)q2)[(size_t)row * (Cw / 4) + c4] = u2;
    }
}

__global__ void zerof(float* p, int n) {
    const int i = blockIdx.x * blockDim.x + threadIdx.x;
    if (i < n) p[i] = 0.f;
}

// partial column-max via atomicMax on float bits (nonneg)
__global__ void wmax_part(const float* __restrict__ W, int K, int N, float* __restrict__ sB) {
    const int col = blockIdx.x * 256 + threadIdx.x;
    const int k0 = blockIdx.y * 512;
    float m = 0.f;
    for (int k = k0; k < k0 + 512; k++)
        m = fmaxf(m, fabsf(W[(size_t)k * N + col]));
    atomicMax((unsigned*)(sB + col), __float_as_uint(m));
}

// transpose + quantize: src [K,N] f32 -> limbs [N,K] int8, using per-col raw max sB
__global__ void tconvq(const float* __restrict__ src, const float* __restrict__ sB,
                       int8_t* __restrict__ d1, int8_t* __restrict__ d2, int K, int N)
{
    __shared__ float t[64][33];
    const int kt = blockIdx.y * 64, nb = blockIdx.x * 32;
    const int tid = threadIdx.x;
    {
        const int c4 = (tid & 7) * 4, r0 = tid >> 3;
#pragma unroll
        for (int p = 0; p < 2; p++) {
            const int r = r0 + p * 32;
            const float4 f = *(const float4*)(src + (size_t)(kt + r) * N + nb + c4);
            t[r][c4] = f.x; t[r][c4 + 1] = f.y; t[r][c4 + 2] = f.z; t[r][c4 + 3] = f.w;
        }
    }
    __syncthreads();
    const int n  = tid >> 3;
    const int kc = (tid & 7) * 8;
    const float inv = 127.f / fmaxf(sB[nb + n], 1e-20f);
    uint32_t u1[2], u2[2];
#pragma unroll
    for (int g = 0; g < 2; g++) {
        float4 f = make_float4(t[kc + 4 * g][n], t[kc + 4 * g + 1][n], t[kc + 4 * g + 2][n], t[kc + 4 * g + 3][n]);
        u1[g] = pack_q1(f, inv, u2[g]);
    }
    const size_t o = ((size_t)(nb + n) * K + kt + kc) / 4;
    *(uint2*)((uint32_t*)d1 + o) = make_uint2(u1[0], u1[1]);
    *(uint2*)((uint32_t*)d2 + o) = make_uint2(u2[0], u2[1]);
}

// batched 4-weight version
__global__ void tconvq4(const float* __restrict__ s0, const float* __restrict__ s1,
                        const float* __restrict__ s2, const float* __restrict__ s3,
                        const float* __restrict__ b0, const float* __restrict__ b1,
                        const float* __restrict__ b2, const float* __restrict__ b3,
                        int8_t* __restrict__ o0a, int8_t* __restrict__ o0b,
                        int8_t* __restrict__ o1a, int8_t* __restrict__ o1b,
                        int8_t* __restrict__ o2a, int8_t* __restrict__ o2b,
                        int8_t* __restrict__ o3a, int8_t* __restrict__ o3b)
{
    const int z = blockIdx.z;
    const float* src = z == 0 ? s0 : z == 1 ? s1 : z == 2 ? s2 : s3;
    const float* sB  = z == 0 ? b0 : z == 1 ? b1 : z == 2 ? b2 : b3;
    int8_t* d1 = z == 0 ? o0a : z == 1 ? o1a : z == 2 ? o2a : o3a;
    int8_t* d2 = z == 0 ? o0b : z == 1 ? o1b : z == 2 ? o2b : o3b;
    const int K = C_, N = H_;

    __shared__ float t[64][33];
    const int kt = blockIdx.y * 64, nb = blockIdx.x * 32;
    const int tid = threadIdx.x;
    {
        const int c4 = (tid & 7) * 4, r0 = tid >> 3;
#pragma unroll
        for (int p = 0; p < 2; p++) {
            const int r = r0 + p * 32;
            const float4 f = *(const float4*)(src + (size_t)(kt + r) * N + nb + c4);
            t[r][c4] = f.x; t[r][c4 + 1] = f.y; t[r][c4 + 2] = f.z; t[r][c4 + 3] = f.w;
        }
    }
    __syncthreads();
    const int n  = tid >> 3;
    const int kc = (tid & 7) * 8;
    const float inv = 127.f / fmaxf(sB[nb + n], 1e-20f);
    uint32_t u1[2], u2[2];
#pragma unroll
    for (int g = 0; g < 2; g++) {
        float4 f = make_float4(t[kc + 4 * g][n], t[kc + 4 * g + 1][n], t[kc + 4 * g + 2][n], t[kc + 4 * g + 3][n]);
        u1[g] = pack_q1(f, inv, u2[g]);
    }
    const size_t o = ((size_t)(nb + n) * K + kt + kc) / 4;
    *(uint2*)((uint32_t*)d1 + o) = make_uint2(u1[0], u1[1]);
    *(uint2*)((uint32_t*)d2 + o) = make_uint2(u2[0], u2[1]);
}

// ---------------- LayerNorm kernels ----------------
// new_h = LN(h*(2-u) + u*silu(g)*up); writes fp32 newh AND int8 limbs + row scale
__global__ void ln_newh(const float* __restrict__ u, const float* __restrict__ h,
                        const float* __restrict__ g, const float* __restrict__ up,
                        const float* __restrict__ gamma, const float* __restrict__ beta,
                        float* __restrict__ out,
                        int8_t* __restrict__ q1, int8_t* __restrict__ q2, float* __restrict__ sOut)
{
    const int row = blockIdx.x, tid = threadIdx.x;
    const int NF = H_ / 1024;  // 4 float4 per thread
    const size_t base = (size_t)row * H_;
    float4 v[4];
    float s = 0.f, ss = 0.f;
#pragma unroll
    for (int t = 0; t < NF; t++) {
        const int c = (t * 256 + tid) * 4;
        const float4 uu = *(const float4*)(u + base + c);
        const float4 hh = *(const float4*)(h + base + c);
        const float4 gg = *(const float4*)(g + base + c);
        const float4 pp = *(const float4*)(up + base + c);
        float4 r;
        r.x = hh.x * (2.f - uu.x) + uu.x * (gg.x * sigm(gg.x)) * pp.x;
        r.y = hh.y * (2.f - uu.y) + uu.y * (gg.y * sigm(gg.y)) * pp.y;
        r.z = hh.z * (2.f - uu.z) + uu.z * (gg.z * sigm(gg.z)) * pp.z;
        r.w = hh.w * (2.f - uu.w) + uu.w * (gg.w * sigm(gg.w)) * pp.w;
        v[t] = r;
        s += r.x + r.y + r.z + r.w;
        ss += r.x * r.x + r.y * r.y + r.z * r.z + r.w * r.w;
    }
    __shared__ float sm[3][8];
#pragma unroll
    for (int o = 16; o > 0; o >>= 1) {
        s  += __shfl_xor_sync(0xffffffffu, s, o);
        ss += __shfl_xor_sync(0xffffffffu, ss, o);
    }
    const int warp = tid >> 5, lane = tid & 31;
    if (lane == 0) { sm[0][warp] = s; sm[1][warp] = ss; }
    __syncthreads();
    float ts = 0.f, tss = 0.f;
#pragma unroll
    for (int w = 0; w < 8; w++) { ts += sm[0][w]; tss += sm[1][w]; }
    const float mean = ts / (float)H_;
    const float var  = tss / (float)H_ - mean * mean;
    const float rstd = rsqrtf(var + LN_EPS);

    float4 r[4];
    float mx = 0.f;
#pragma unroll
    for (int t = 0; t < NF; t++) {
        const int c = (t * 256 + tid) * 4;
        const float4 gm = *(const float4*)(gamma + c);
        const float4 bt = *(const float4*)(beta + c);
        r[t].x = (v[t].x - mean) * rstd * gm.x + bt.x;
        r[t].y = (v[t].y - mean) * rstd * gm.y + bt.y;
        r[t].z = (v[t].z - mean) * rstd * gm.z + bt.z;
        r[t].w = (v[t].w - mean) * rstd * gm.w + bt.w;
        *(float4*)(out + base + c) = r[t];
        mx = fmaxf(mx, fmaxf(fmaxf(fabsf(r[t].x), fabsf(r[t].y)), fmaxf(fabsf(r[t].z), fabsf(r[t].w))));
    }
#pragma unroll
    for (int o = 16; o > 0; o >>= 1) mx = fmaxf(mx, __shfl_xor_sync(0xffffffffu, mx, o));
    if (lane == 0) sm[2][warp] = mx;
    __syncthreads();
    float gmx = 0.f;
#pragma unroll
    for (int w = 0; w < 8; w++) gmx = fmaxf(gmx, sm[2][w]);
    gmx = fmaxf(gmx, 1e-20f);
    if (tid == 0) sOut[row] = gmx * (1.f / 127.f);
    const float inv = 127.f / gmx;
#pragma unroll
    for (int t = 0; t < NF; t++) {
        const int c4 = t * 256 + tid;
        uint32_t u2;
        const uint32_t u1 = pack_q1(r[t], inv, u2);
        ((uint32_t*)q1)[base / 4 + c4] = u1;
        ((uint32_t*)q2)[base / 4 + c4] = u2;
    }
}

__global__ void ln_out(const float* __restrict__ in,
                       const float* __restrict__ bd,
                       const float* __restrict__ gamma, const float* __restrict__ beta,
                       float* __restrict__ out)
{
    const int row = blockIdx.x, tid = threadIdx.x;
    const int PER = D_ / 256;
    const size_t base = (size_t)row * D_;
    const size_t zoff = (size_t)B_ * D_;
    float v[PER];
    float s = 0.f, ss = 0.f;
#pragma unroll
    for (int i = 0; i < PER; i++) {
        const int j = i * 256 + tid;
        float val = bd[j];
#pragma unroll
        for (int z = 0; z < KSLICE_D; z++) val += in[z * zoff + base + j];
        v[i] = val; s += val; ss += val * val;
    }
    __shared__ float sm[2][8];
#pragma unroll
    for (int o = 16; o > 0; o >>= 1) {
        s  += __shfl_xor_sync(0xffffffffu, s, o);
        ss += __shfl_xor_sync(0xffffffffu, ss, o);
    }
    const int warp = tid >> 5, lane = tid & 31;
    if (lane == 0) { sm[0][warp] = s; sm[1][warp] = ss; }
    __syncthreads();
    float ts = 0.f, tss = 0.f;
#pragma unroll
    for (int w = 0; w < 8; w++) { ts += sm[0][w]; tss += sm[1][w]; }
    const float mean = ts / (float)D_;
    const float var  = tss / (float)D_ - mean * mean;
    const float rstd = rsqrtf(var + LN_EPS);
#pragma unroll
    for (int i = 0; i < PER; i++) {
        const int j = i * 256 + tid;
        out[base + j] = (v[i] - mean) * rstd * gamma[j] + beta[j];
    }
}

// ---------------- host ----------------
extern "C" void kernel_launch(void* const* d_in, const int* in_sizes, int n_in,
                              void* d_out, int out_size)
{
    const float* x    = (const float*)d_in[0];
    const float* h    = (const float*)d_in[1];
    const float* W_u  = (const float*)d_in[2];
    const float* b_u  = (const float*)d_in[3];
    const float* W_r  = (const float*)d_in[4];
    const float* b_r  = (const float*)d_in[5];
    const float* W_g  = (const float*)d_in[6];
    const float* b_g  = (const float*)d_in[7];
    const float* W_up = (const float*)d_in[8];
    const float* b_up = (const float*)d_in[9];
    const float* W_d  = (const float*)d_in[10];
    const float* b_d  = (const float*)d_in[11];
    const float* g_hh = (const float*)d_in[12];
    const float* be_h = (const float*)d_in[13];
    const float* g_o  = (const float*)d_in[14];
    const float* be_o = (const float*)d_in[15];
    float* out = (float*)d_out;

    void *pwu1, *pwu2, *pwr1, *pwr2, *pwg1, *pwg2, *pwp1, *pwp2, *pwd1, *pwd2;
    void *pxa1, *pxa2, *pya1, *pya2, *pza1, *pza2;
    float *psa1, *psa2, *psa3, *psbu, *psbr, *psbg, *psbp, *psbd;
    float *pu, *prh, *pg, *pup, *pnh, *pdo;
    cudaGetSymbolAddress(&pwu1, g_wu1); cudaGetSymbolAddress(&pwu2, g_wu2);
    cudaGetSymbolAddress(&pwr1, g_wr1); cudaGetSymbolAddress(&pwr2, g_wr2);
    cudaGetSymbolAddress(&pwg1, g_wg1); cudaGetSymbolAddress(&pwg2, g_wg2);
    cudaGetSymbolAddress(&pwp1, g_wp1); cudaGetSymbolAddress(&pwp2, g_wp2);
    cudaGetSymbolAddress(&pwd1, g_wd1); cudaGetSymbolAddress(&pwd2, g_wd2);
    cudaGetSymbolAddress(&pxa1, g_xa1); cudaGetSymbolAddress(&pxa2, g_xa2);
    cudaGetSymbolAddress(&pya1, g_ya1); cudaGetSymbolAddress(&pya2, g_ya2);
    cudaGetSymbolAddress(&pza1, g_za1); cudaGetSymbolAddress(&pza2, g_za2);
    cudaGetSymbolAddress((void**)&psa1, g_sa1); cudaGetSymbolAddress((void**)&psa2, g_sa2);
    cudaGetSymbolAddress((void**)&psa3, g_sa3);
    cudaGetSymbolAddress((void**)&psbu, g_sbu); cudaGetSymbolAddress((void**)&psbr, g_sbr);
    cudaGetSymbolAddress((void**)&psbg, g_sbg); cudaGetSymbolAddress((void**)&psbp, g_sbp);
    cudaGetSymbolAddress((void**)&psbd, g_sbd);
    cudaGetSymbolAddress((void**)&pu,  g_u);  cudaGetSymbolAddress((void**)&prh, g_rh);
    cudaGetSymbolAddress((void**)&pg,  g_g);  cudaGetSymbolAddress((void**)&pup, g_up);
    cudaGetSymbolAddress((void**)&pnh, g_nh); cudaGetSymbolAddress((void**)&pdo, g_do);

    constexpr int SMEM = STG * (int)STAGE_BYTES;  // 98304
    cudaFuncSetAttribute((const void*)gemm_imma<0>, cudaFuncAttributeMaxDynamicSharedMemorySize, SMEM);
    cudaFuncSetAttribute((const void*)gemm_imma<1>, cudaFuncAttributeMaxDynamicSharedMemorySize, SMEM);
    cudaFuncSetAttribute((const void*)gemm_imma<2>, cudaFuncAttributeMaxDynamicSharedMemorySize, SMEM);

    float* newh = (out_size >= B_ * (D_ + H_)) ? (out + (size_t)B_ * D_) : pnh;

    // weight col-max (raw max into sB via atomicMax on float bits)
    zerof<<<(H_ + 255) / 256, 256>>>(psbu, H_);
    zerof<<<(H_ + 255) / 256, 256>>>(psbr, H_);
    zerof<<<(H_ + 255) / 256, 256>>>(psbg, H_);
    zerof<<<(H_ + 255) / 256, 256>>>(psbp, H_);
    zerof<<<(D_ + 255) / 256, 256>>>(psbd, D_);
    wmax_part<<<dim3(H_ / 256, C_ / 512), 256>>>(W_u,  C_, H_, psbu);
    wmax_part<<<dim3(H_ / 256, C_ / 512), 256>>>(W_r,  C_, H_, psbr);
    wmax_part<<<dim3(H_ / 256, C_ / 512), 256>>>(W_g,  C_, H_, psbg);
    wmax_part<<<dim3(H_ / 256, C_ / 512), 256>>>(W_up, C_, H_, psbp);
    wmax_part<<<dim3(D_ / 256, H_ / 512), 256>>>(W_d,  H_, D_, psbd);

    // weight transpose + quantize
    tconvq4<<<dim3(H_ / 32, C_ / 64, 4), 256>>>(
        W_u, W_r, W_g, W_up, psbu, psbr, psbg, psbp,
        (int8_t*)pwu1, (int8_t*)pwu2, (int8_t*)pwr1, (int8_t*)pwr2,
        (int8_t*)pwg1, (int8_t*)pwg2, (int8_t*)pwp1, (int8_t*)pwp2);
    tconvq<<<dim3(D_ / 32, H_ / 64), 256>>>(W_d, psbd, (int8_t*)pwd1, (int8_t*)pwd2, H_, D_);

    // activation quantize: A1 = [x|h]
    quant_act<<<B_, 256>>>(x, D_, h, H_, (int8_t*)pxa1, (int8_t*)pxa2, psa1);

    // GEMM1: u + rh
    gemm_imma<0><<<dim3(64, 8, 1), 256, SMEM>>>(
        (const int8_t*)pxa1, (const int8_t*)pxa2, psa1, C_,
        (const int8_t*)pwu1, (const int8_t*)pwu2, psbu,
        (const int8_t*)pwr1, (const int8_t*)pwr2, psbr, C_,
        b_u, b_r, h, pu, nullptr, prh, C_, 32, 1);

    // A2 = [x|rh]
    quant_act<<<B_, 256>>>(x, D_, prh, H_, (int8_t*)pya1, (int8_t*)pya2, psa2);

    // GEMM2: g + up
    gemm_imma<1><<<dim3(64, 8, 1), 256, SMEM>>>(
        (const int8_t*)pya1, (const int8_t*)pya2, psa2, C_,
        (const int8_t*)pwg1, (const int8_t*)pwg2, psbg,
        (const int8_t*)pwp1, (const int8_t*)pwp2, psbp, C_,
        b_g, b_up, nullptr, pg, pup, nullptr, C_, 32, 1);

    // LN + quantize new_h
    ln_newh<<<B_, 256>>>(pu, h, pg, pup, g_hh, be_h, newh,
                         (int8_t*)pza1, (int8_t*)pza2, psa3);

    // down projection (split-K x4)
    gemm_imma<2><<<dim3(8, 8, KSLICE_D), 256, SMEM>>>(
        (const int8_t*)pza1, (const int8_t*)pza2, psa3, H_,
        (const int8_t*)pwd1, (const int8_t*)pwd2, psbd,
        (const int8_t*)pwd1, (const int8_t*)pwd2, psbd, H_,
        b_d, b_d, nullptr, pdo, nullptr, nullptr, H_, 1000, KSLICE_D);

    ln_out<<<B_, 256>>>(pdo, b_d, g_o, be_o, out);
}

// round 9
// speedup vs baseline: 3.5571x; 3.5571x over previous
#include <cuda_runtime.h>
#include <cuda_fp16.h>
#include <math.h>
#include <stdint.h>

#define B_ 1024
#define D_ 1024
#define H_ 4096
#define C_ 5120
#define LN_EPS 1e-3f
#define KSLICE_D 4

// ---------------- scratch (device globals: allocation-free) ----------------
__device__ __align__(1024) __half g_a1h[B_ * C_], g_a1l[B_ * C_];
__device__ __align__(1024) __half g_a2h[B_ * C_], g_a2l[B_ * C_];
__device__ __align__(1024) __half g_a3h[B_ * H_], g_a3l[B_ * H_];
__device__ __align__(1024) __half g_wu[(long)H_ * C_];
__device__ __align__(1024) __half g_wr[(long)H_ * C_];
__device__ __align__(1024) __half g_wg[(long)H_ * C_];
__device__ __align__(1024) __half g_wp[(long)H_ * C_];
__device__ __align__(1024) __half g_wd[(long)D_ * H_];
__device__ float g_u [B_ * H_];
__device__ float g_g [B_ * H_];
__device__ float g_up[B_ * H_];
__device__ float g_nh[B_ * H_];
__device__ float g_do[KSLICE_D * B_ * D_];

// ---------------- helpers ----------------
__device__ __forceinline__ uint32_t smem_u32(const void* p) {
    uint32_t a;
    asm("{ .reg .u64 t; cvta.to.shared.u64 t, %1; cvt.u32.u64 %0, t; }" : "=r"(a) : "l"(p));
    return a;
}
__device__ __forceinline__ void cp16(uint32_t dst, const void* src) {
    asm volatile("cp.async.cg.shared.global [%0], [%1], 16;" :: "r"(dst), "l"(src) : "memory");
}
__device__ __forceinline__ void ldsm_x4(uint32_t* r, uint32_t addr) {
    asm volatile("ldmatrix.sync.aligned.m8n8.x4.shared.b16 {%0,%1,%2,%3}, [%4];"
                 : "=r"(r[0]), "=r"(r[1]), "=r"(r[2]), "=r"(r[3]) : "r"(addr));
}
__device__ __forceinline__ void mma16816(float* c, const uint32_t* a, uint32_t b0, uint32_t b1) {
    asm volatile(
        "mma.sync.aligned.m16n8k16.row.col.f32.f16.f16.f32 "
        "{%0,%1,%2,%3}, {%4,%5,%6,%7}, {%8,%9}, {%0,%1,%2,%3};"
        : "+f"(c[0]), "+f"(c[1]), "+f"(c[2]), "+f"(c[3])
        : "r"(a[0]), "r"(a[1]), "r"(a[2]), "r"(a[3]), "r"(b0), "r"(b1));
}
__device__ __forceinline__ void split_h(float f, __half& hi, __half& lo) {
    hi = __float2half_rn(f);
    lo = __float2half_rn(f - __half2float(hi));
}
__device__ __forceinline__ float sigm(float x) { return 1.0f / (1.0f + expf(-x)); }

// swizzled offset inside a [128 rows][32 fp16] tile (64B rows, 16B chunks)
__device__ __forceinline__ uint32_t sw_off(int row, int cb) {
    return (uint32_t)row * 64u + (uint32_t)((cb ^ ((row >> 1) & 3)) << 4);
}

// ---------------- fp16 2-term HMMA GEMM (2 CTAs/SM) ----------------
#define KT 32
#define STG 3
#define STAGE_BYTES 24576u   // Ah(0) Al(8192) B(16384), each 128x32 fp16 = 8KB

template<int MODE>
__global__ void __launch_bounds__(256, 2) gemm_hmma(
    const __half* __restrict__ Ah, const __half* __restrict__ Al, int ldA,
    const __half* __restrict__ B0, const __half* __restrict__ B1, int ldB,
    const float* __restrict__ bias0, const float* __restrict__ bias1,
    const float* __restrict__ hmul,
    float* __restrict__ fout0, float* __restrict__ fout1,
    __half* __restrict__ obh, __half* __restrict__ obl,
    int K, int nhalf, int kslices)
{
    extern __shared__ __align__(1024) char smraw[];
    const uint32_t sb = smem_u32(smraw);

    const int tid = threadIdx.x, lane = tid & 31, wid = tid >> 5;
    const int wm = (wid >> 2) * 64;
    const int wn = (wid & 3) * 32;
    const int nt = blockIdx.x, mt = blockIdx.y;
    const bool second = nt >= nhalf;
    const int ntin = second ? nt - nhalf : nt;
    const __half* Bp = second ? B1 : B0;
    const float* bias = second ? bias1 : bias0;

    const int m0 = mt * 128, n0 = ntin * 128;
    const int Ks = K / kslices;
    const int kbeg = blockIdx.z * Ks;
    const int S = Ks / KT;

    // ---- stage loader: 3 tiles of [128 rows][32 fp16] ----
    const int lr  = tid >> 1;
    const int lcb = (tid & 1) * 2;
    auto load_stage = [&](int slot, int kk) {
        const uint32_t tb = sb + (uint32_t)slot * STAGE_BYTES;
        const size_t arow = (size_t)(m0 + lr) * ldA + kk;
        const size_t brow = (size_t)(n0 + lr) * ldB + kk;
#pragma unroll
        for (int c = 0; c < 2; c++) {
            const int cb = lcb + c;
            const uint32_t sw = tb + sw_off(lr, cb);
            cp16(sw,          Ah + arow + cb * 8);
            cp16(sw + 8192,   Al + arow + cb * 8);
            cp16(sw + 16384,  Bp + brow + cb * 8);
        }
    };

    // precomputed ldsm offsets (s=0 chunk; s=1 is off ^ 32)
    const int lb = (lane >> 4) & 1;
    uint32_t offA[4], offB[2];
#pragma unroll
    for (int i = 0; i < 4; i++) offA[i] = sw_off(wm + i * 16 + (lane & 15), lb);
#pragma unroll
    for (int jp = 0; jp < 2; jp++) offB[jp] = sw_off(wn + jp * 16 + (lane & 15), lb);

    // prologue
#pragma unroll
    for (int s = 0; s < STG - 1; s++) {
        if (s < S) load_stage(s, kbeg + s * KT);
        asm volatile("cp.async.commit_group;" ::: "memory");
    }

    float acc[4][4][4];
#pragma unroll
    for (int i = 0; i < 4; i++)
#pragma unroll
        for (int j = 0; j < 4; j++)
#pragma unroll
            for (int e = 0; e < 4; e++) acc[i][j][e] = 0.f;

    for (int ks = 0; ks < S; ks++) {
        asm volatile("cp.async.wait_group 1;" ::: "memory");
        __syncthreads();
        if (ks + STG - 1 < S) load_stage((ks + STG - 1) % STG, kbeg + (ks + STG - 1) * KT);
        asm volatile("cp.async.commit_group;" ::: "memory");

        const uint32_t base = sb + (uint32_t)(ks % STG) * STAGE_BYTES;
#pragma unroll
        for (int s = 0; s < 2; s++) {
            const uint32_t sx = (uint32_t)(s << 5);
            uint32_t ah[4][4], b[2][4];
#pragma unroll
            for (int i = 0; i < 4; i++)   ldsm_x4(ah[i], base + (offA[i] ^ sx));
#pragma unroll
            for (int jp = 0; jp < 2; jp++) ldsm_x4(b[jp], base + 16384 + (offB[jp] ^ sx));
            // term Ah*B
#pragma unroll
            for (int i = 0; i < 4; i++)
#pragma unroll
                for (int j = 0; j < 4; j++)
                    mma16816(acc[i][j], ah[i], b[j >> 1][j & 1], b[j >> 1][2 | (j & 1)]);
            // prefetch Al under the MMAs
            uint32_t al[4][4];
#pragma unroll
            for (int i = 0; i < 4; i++)   ldsm_x4(al[i], base + 8192 + (offA[i] ^ sx));
            // term Al*B
#pragma unroll
            for (int i = 0; i < 4; i++)
#pragma unroll
                for (int j = 0; j < 4; j++)
                    mma16816(acc[i][j], al[i], b[j >> 1][j & 1], b[j >> 1][2 | (j & 1)]);
        }
    }

    // ---- epilogue ----
#pragma unroll
    for (int i = 0; i < 4; i++) {
#pragma unroll
        for (int j = 0; j < 4; j++) {
            const int r0 = m0 + wm + i * 16 + (lane >> 2);
            const int gc = ntin * 128 + wn + j * 8 + 2 * (lane & 3);
#pragma unroll
            for (int half = 0; half < 2; half++) {
                const int row = r0 + half * 8;
                const float v0r = acc[i][j][half * 2];
                const float v1r = acc[i][j][half * 2 + 1];
                if (MODE == 0) {
                    const float v0 = v0r + bias[gc], v1 = v1r + bias[gc + 1];
                    if (!second) {
                        fout0[(long)row * H_ + gc]     = sigm(v0);
                        fout0[(long)row * H_ + gc + 1] = sigm(v1);
                    } else {
                        const float rh0 = sigm(v0) * hmul[(long)row * H_ + gc];
                        const float rh1 = sigm(v1) * hmul[(long)row * H_ + gc + 1];
                        __half h0, l0, h1, l1;
                        split_h(rh0, h0, l0);
                        split_h(rh1, h1, l1);
                        obh[(long)row * C_ + D_ + gc]     = h0;
                        obl[(long)row * C_ + D_ + gc]     = l0;
                        obh[(long)row * C_ + D_ + gc + 1] = h1;
                        obl[(long)row * C_ + D_ + gc + 1] = l1;
                    }
                } else if (MODE == 1) {
                    float* dst = second ? fout1 : fout0;
                    dst[(long)row * H_ + gc]     = v0r + bias[gc];
                    dst[(long)row * H_ + gc + 1] = v1r + bias[gc + 1];
                } else {
                    float* dst = fout0 + (size_t)blockIdx.z * B_ * D_;
                    dst[(long)row * D_ + gc]     = v0r;
                    dst[(long)row * D_ + gc + 1] = v1r;
                }
            }
        }
    }
}

// ---------------- conversion kernels ----------------
__global__ void conv_a1(const float* __restrict__ x, const float* __restrict__ h,
                        __half* __restrict__ a1h, __half* __restrict__ a1l,
                        __half* __restrict__ a2h, __half* __restrict__ a2l)
{
    const long i4 = (long)blockIdx.x * blockDim.x + threadIdx.x;
    if (i4 >= (long)B_ * C_ / 4) return;
    const int row = (int)(i4 / (C_ / 4));
    const int c = (int)(i4 % (C_ / 4)) * 4;
    float4 f;
    if (c < D_) f = *(const float4*)(x + (long)row * D_ + c);
    else        f = *(const float4*)(h + (long)row * H_ + (c - D_));
    __half h0, l0, h1, l1, h2, l2, h3, l3;
    split_h(f.x, h0, l0); split_h(f.y, h1, l1);
    split_h(f.z, h2, l2); split_h(f.w, h3, l3);
    __half2 hv0 = __halves2half2(h0, h1), hv1 = __halves2half2(h2, h3);
    __half2 lv0 = __halves2half2(l0, l1), lv1 = __halves2half2(l2, l3);
    const long o = (long)row * C_ + c;
    *(uint2*)(a1h + o) = make_uint2(*(uint32_t*)&hv0, *(uint32_t*)&hv1);
    *(uint2*)(a1l + o) = make_uint2(*(uint32_t*)&lv0, *(uint32_t*)&lv1);
    if (c < D_) {
        *(uint2*)(a2h + o) = make_uint2(*(uint32_t*)&hv0, *(uint32_t*)&hv1);
        *(uint2*)(a2l + o) = make_uint2(*(uint32_t*)&lv0, *(uint32_t*)&lv1);
    }
}

// batched transpose + round to fp16 (single limb) for the 4 big weights
__global__ void tconv4(const float* __restrict__ s0, const float* __restrict__ s1,
                       const float* __restrict__ s2, const float* __restrict__ s3,
                       __half* __restrict__ d0, __half* __restrict__ d1,
                       __half* __restrict__ d2, __half* __restrict__ d3)
{
    const int z = blockIdx.z;
    const float* src = z == 0 ? s0 : z == 1 ? s1 : z == 2 ? s2 : s3;
    __half* dh = z == 0 ? d0 : z == 1 ? d1 : z == 2 ? d2 : d3;
    const int K = C_, N = H_;

    __shared__ float t[64][33];
    const int kt = blockIdx.y * 64, nb = blockIdx.x * 32;
    const int tid = threadIdx.x;
    {
        const int c4 = (tid & 7) * 4, r0 = tid >> 3;
#pragma unroll
        for (int p = 0; p < 2; p++) {
            const int r = r0 + p * 32;
            const float4 f = *(const float4*)(src + (size_t)(kt + r) * N + nb + c4);
            t[r][c4] = f.x; t[r][c4 + 1] = f.y; t[r][c4 + 2] = f.z; t[r][c4 + 3] = f.w;
        }
    }
    __syncthreads();
    const int n  = tid >> 3;
    const int k8 = (tid & 7) * 8;
    __half2 hv[4];
#pragma unroll
    for (int i = 0; i < 4; i++)
        hv[i] = __halves2half2(__float2half_rn(t[k8 + 2 * i][n]), __float2half_rn(t[k8 + 2 * i + 1][n]));
    const long o = (long)(nb + n) * K + kt + k8;
    *(uint4*)(dh + o) = make_uint4(*(uint32_t*)&hv[0], *(uint32_t*)&hv[1],
                                   *(uint32_t*)&hv[2], *(uint32_t*)&hv[3]);
}

__global__ void tconv(const float* __restrict__ src, __half* __restrict__ dh, int K, int N)
{
    __shared__ float t[64][33];
    const int kt = blockIdx.y * 64, nb = blockIdx.x * 32;
    const int tid = threadIdx.x;
    {
        const int c4 = (tid & 7) * 4, r0 = tid >> 3;
#pragma unroll
        for (int p = 0; p < 2; p++) {
            const int r = r0 + p * 32;
            const float4 f = *(const float4*)(src + (size_t)(kt + r) * N + nb + c4);
            t[r][c4] = f.x; t[r][c4 + 1] = f.y; t[r][c4 + 2] = f.z; t[r][c4 + 3] = f.w;
        }
    }
    __syncthreads();
    const int n  = tid >> 3;
    const int k8 = (tid & 7) * 8;
    __half2 hv[4];
#pragma unroll
    for (int i = 0; i < 4; i++)
        hv[i] = __halves2half2(__float2half_rn(t[k8 + 2 * i][n]), __float2half_rn(t[k8 + 2 * i + 1][n]));
    const long o = (long)(nb + n) * K + kt + k8;
    *(uint4*)(dh + o) = make_uint4(*(uint32_t*)&hv[0], *(uint32_t*)&hv[1],
                                   *(uint32_t*)&hv[2], *(uint32_t*)&hv[3]);
}

// ---------------- LayerNorm kernels ----------------
__global__ void ln_newh(const float* __restrict__ u, const float* __restrict__ h,
                        const float* __restrict__ g, const float* __restrict__ up,
                        const float* __restrict__ gamma, const float* __restrict__ beta,
                        float* __restrict__ out,
                        __half* __restrict__ a3h, __half* __restrict__ a3l)
{
    const int row = blockIdx.x, tid = threadIdx.x;
    const int PER = H_ / 256;
    const long base = (long)row * H_;
    float v[PER];
    float s = 0.f, ss = 0.f;
#pragma unroll
    for (int i = 0; i < PER; i++) {
        const int j = i * 256 + tid;
        const float uu = u[base + j];
        const float gg = g[base + j];
        const float val = h[base + j] * (2.f - uu) + uu * (gg * sigm(gg)) * up[base + j];
        v[i] = val; s += val; ss += val * val;
    }
    __shared__ float sm[2][8];
#pragma unroll
    for (int o = 16; o > 0; o >>= 1) {
        s  += __shfl_xor_sync(0xffffffffu, s, o);
        ss += __shfl_xor_sync(0xffffffffu, ss, o);
    }
    const int warp = tid >> 5, lane = tid & 31;
    if (lane == 0) { sm[0][warp] = s; sm[1][warp] = ss; }
    __syncthreads();
    float ts = 0.f, tss = 0.f;
#pragma unroll
    for (int w = 0; w < 8; w++) { ts += sm[0][w]; tss += sm[1][w]; }
    const float mean = ts / (float)H_;
    const float var  = tss / (float)H_ - mean * mean;
    const float rstd = rsqrtf(var + LN_EPS);
#pragma unroll
    for (int i = 0; i < PER; i++) {
        const int j = i * 256 + tid;
        const float r = (v[i] - mean) * rstd * gamma[j] + beta[j];
        out[base + j] = r;
        __half hi, lo;
        split_h(r, hi, lo);
        a3h[base + j] = hi; a3l[base + j] = lo;
    }
}

__global__ void ln_out(const float* __restrict__ in,
                       const float* __restrict__ bd,
                       const float* __restrict__ gamma, const float* __restrict__ beta,
                       float* __restrict__ out)
{
    const int row = blockIdx.x, tid = threadIdx.x;
    const int PER = D_ / 256;
    const long base = (long)row * D_;
    const long zoff = (long)B_ * D_;
    float v[PER];
    float s = 0.f, ss = 0.f;
#pragma unroll
    for (int i = 0; i < PER; i++) {
        const int j = i * 256 + tid;
        float val = bd[j];
#pragma unroll
        for (int z = 0; z < KSLICE_D; z++) val += in[z * zoff + base + j];
        v[i] = val; s += val; ss += val * val;
    }
    __shared__ float sm[2][8];
#pragma unroll
    for (int o = 16; o > 0; o >>= 1) {
        s  += __shfl_xor_sync(0xffffffffu, s, o);
        ss += __shfl_xor_sync(0xffffffffu, ss, o);
    }
    const int warp = tid >> 5, lane = tid & 31;
    if (lane == 0) { sm[0][warp] = s; sm[1][warp] = ss; }
    __syncthreads();
    float ts = 0.f, tss = 0.f;
#pragma unroll
    for (int w = 0; w < 8; w++) { ts += sm[0][w]; tss += sm[1][w]; }
    const float mean = ts / (float)D_;
    const float var  = tss / (float)D_ - mean * mean;
    const float rstd = rsqrtf(var + LN_EPS);
#pragma unroll
    for (int i = 0; i < PER; i++) {
        const int j = i * 256 + tid;
        out[base + j] = (v[i] - mean) * rstd * gamma[j] + beta[j];
    }
}

// ---------------- host ----------------
extern "C" void kernel_launch(void* const* d_in, const int* in_sizes, int n_in,
                              void* d_out, int out_size)
{
    const float* x    = (const float*)d_in[0];
    const float* h    = (const float*)d_in[1];
    const float* W_u  = (const float*)d_in[2];
    const float* b_u  = (const float*)d_in[3];
    const float* W_r  = (const float*)d_in[4];
    const float* b_r  = (const float*)d_in[5];
    const float* W_g  = (const float*)d_in[6];
    const float* b_g  = (const float*)d_in[7];
    const float* W_up = (const float*)d_in[8];
    const float* b_up = (const float*)d_in[9];
    const float* W_d  = (const float*)d_in[10];
    const float* b_d  = (const float*)d_in[11];
    const float* g_hh = (const float*)d_in[12];
    const float* be_h = (const float*)d_in[13];
    const float* g_o  = (const float*)d_in[14];
    const float* be_o = (const float*)d_in[15];
    float* out = (float*)d_out;

    void *pa1h, *pa1l, *pa2h, *pa2l, *pa3h, *pa3l;
    void *pwu, *pwr, *pwg, *pwp, *pwd;
    float *pu, *pg, *pup, *pnh, *pdo;
    cudaGetSymbolAddress(&pa1h, g_a1h); cudaGetSymbolAddress(&pa1l, g_a1l);
    cudaGetSymbolAddress(&pa2h, g_a2h); cudaGetSymbolAddress(&pa2l, g_a2l);
    cudaGetSymbolAddress(&pa3h, g_a3h); cudaGetSymbolAddress(&pa3l, g_a3l);
    cudaGetSymbolAddress(&pwu, g_wu); cudaGetSymbolAddress(&pwr, g_wr);
    cudaGetSymbolAddress(&pwg, g_wg); cudaGetSymbolAddress(&pwp, g_wp);
    cudaGetSymbolAddress(&pwd, g_wd);
    cudaGetSymbolAddress((void**)&pu,  g_u);
    cudaGetSymbolAddress((void**)&pg,  g_g);
    cudaGetSymbolAddress((void**)&pup, g_up);
    cudaGetSymbolAddress((void**)&pnh, g_nh);
    cudaGetSymbolAddress((void**)&pdo, g_do);

    constexpr int SMEM = STG * (int)STAGE_BYTES;  // 73728 -> 2 CTAs/SM
    cudaFuncSetAttribute((const void*)gemm_hmma<0>, cudaFuncAttributeMaxDynamicSharedMemorySize, SMEM);
    cudaFuncSetAttribute((const void*)gemm_hmma<1>, cudaFuncAttributeMaxDynamicSharedMemorySize, SMEM);
    cudaFuncSetAttribute((const void*)gemm_hmma<2>, cudaFuncAttributeMaxDynamicSharedMemorySize, SMEM);

    float* newh = (out_size >= B_ * (D_ + H_)) ? (out + (long)B_ * D_) : pnh;

    conv_a1<<<(unsigned)(((long)B_ * C_ / 4 + 255) / 256), 256>>>(
        x, h, (__half*)pa1h, (__half*)pa1l, (__half*)pa2h, (__half*)pa2l);

    tconv4<<<dim3(H_ / 32, C_ / 64, 4), 256>>>(
        W_u, W_r, W_g, W_up,
        (__half*)pwu, (__half*)pwr, (__half*)pwg, (__half*)pwp);
    tconv<<<dim3(D_ / 32, H_ / 64), 256>>>(W_d, (__half*)pwd, H_, D_);

    // u = sigmoid([x|h]Wu+bu);  rh = sigmoid([x|h]Wr+br)*h -> fp16 split into A2
    gemm_hmma<0><<<dim3(64, 8, 1), 256, SMEM>>>(
        (const __half*)pa1h, (const __half*)pa1l, C_,
        (const __half*)pwu, (const __half*)pwr, C_,
        b_u, b_r, h, pu, nullptr,
        (__half*)pa2h, (__half*)pa2l, C_, 32, 1);

    // g = [x|rh]Wg+bg ; up = [x|rh]Wup+bup (raw f32)
    gemm_hmma<1><<<dim3(64, 8, 1), 256, SMEM>>>(
        (const __half*)pa2h, (const __half*)pa2l, C_,
        (const __half*)pwg, (const __half*)pwp, C_,
        b_g, b_up, nullptr, pg, pup, nullptr, nullptr, C_, 32, 1);

    ln_newh<<<B_, 256>>>(pu, h, pg, pup, g_hh, be_h, newh,
                         (__half*)pa3h, (__half*)pa3l);

    // down: new_h @ W_d (split-K x4, raw partials)
    gemm_hmma<2><<<dim3(8, 8, KSLICE_D), 256, SMEM>>>(
        (const __half*)pa3h, (const __half*)pa3l, H_,
        (const __half*)pwd, (const __half*)pwd, H_,
        b_d, b_d, nullptr, pdo, nullptr, nullptr, nullptr, H_, 1000, KSLICE_D);

    ln_out<<<B_, 256>>>(pdo, b_d, g_o, be_o, out);
}

// round 10
// speedup vs baseline: 3.5598x; 1.0008x over previous
#include <cuda_runtime.h>
#include <cuda_fp16.h>
#include <math.h>
#include <stdint.h>

#define B_ 1024
#define D_ 1024
#define H_ 4096
#define C_ 5120
#define LN_EPS 1e-3f
#define KSLICE_D 4

// ---------------- scratch (device globals: allocation-free) ----------------
__device__ __align__(1024) __half g_a1h[B_ * C_], g_a1l[B_ * C_];
__device__ __align__(1024) __half g_a2h[B_ * C_], g_a2l[B_ * C_];
__device__ __align__(1024) __half g_a3h[B_ * H_], g_a3l[B_ * H_];
__device__ __align__(1024) __half g_wu[(long)H_ * C_];
__device__ __align__(1024) __half g_wr[(long)H_ * C_];
__device__ __align__(1024) __half g_wg[(long)H_ * C_];
__device__ __align__(1024) __half g_wp[(long)H_ * C_];
__device__ __align__(1024) __half g_wd[(long)D_ * H_];
__device__ float g_u [B_ * H_];
__device__ float g_g [B_ * H_];
__device__ float g_up[B_ * H_];
__device__ float g_nh[B_ * H_];
__device__ float g_do[KSLICE_D * B_ * D_];

// ---------------- helpers ----------------
__device__ __forceinline__ uint32_t smem_u32(const void* p) {
    uint32_t a;
    asm("{ .reg .u64 t; cvta.to.shared.u64 t, %1; cvt.u32.u64 %0, t; }" : "=r"(a) : "l"(p));
    return a;
}
__device__ __forceinline__ void cp16(uint32_t dst, const void* src) {
    asm volatile("cp.async.cg.shared.global [%0], [%1], 16;" :: "r"(dst), "l"(src) : "memory");
}
__device__ __forceinline__ void ldsm_x4(uint32_t* r, uint32_t addr) {
    asm volatile("ldmatrix.sync.aligned.m8n8.x4.shared.b16 {%0,%1,%2,%3}, [%4];"
                 : "=r"(r[0]), "=r"(r[1]), "=r"(r[2]), "=r"(r[3]) : "r"(addr));
}
// f32-accumulate HMMA
__device__ __forceinline__ void mma_f32(float* c, const uint32_t* a, uint32_t b0, uint32_t b1) {
    asm volatile(
        "mma.sync.aligned.m16n8k16.row.col.f32.f16.f16.f32 "
        "{%0,%1,%2,%3}, {%4,%5,%6,%7}, {%8,%9}, {%0,%1,%2,%3};"
        : "+f"(c[0]), "+f"(c[1]), "+f"(c[2]), "+f"(c[3])
        : "r"(a[0]), "r"(a[1]), "r"(a[2]), "r"(a[3]), "r"(b0), "r"(b1));
}
// f16-accumulate HMMA (2x rate hypothesis); c = 2 regs of f16x2
__device__ __forceinline__ void mma_f16(uint32_t* c, const uint32_t* a, uint32_t b0, uint32_t b1) {
    asm volatile(
        "mma.sync.aligned.m16n8k16.row.col.f16.f16.f16.f16 "
        "{%0,%1}, {%2,%3,%4,%5}, {%6,%7}, {%0,%1};"
        : "+r"(c[0]), "+r"(c[1])
        : "r"(a[0]), "r"(a[1]), "r"(a[2]), "r"(a[3]), "r"(b0), "r"(b1));
}
__device__ __forceinline__ void split_h(float f, __half& hi, __half& lo) {
    hi = __float2half_rn(f);
    lo = __float2half_rn(f - __half2float(hi));
}
__device__ __forceinline__ float sigm(float x) { return 1.0f / (1.0f + expf(-x)); }

// swizzled offset inside a [128 rows][32 fp16] tile (64B rows, 16B chunks)
__device__ __forceinline__ uint32_t sw_off(int row, int cb) {
    return (uint32_t)row * 64u + (uint32_t)((cb ^ ((row >> 1) & 3)) << 4);
}

// ---------------- fp16 2-term HMMA GEMM (hi: f32-acc, lo: f16-acc) ----------------
#define KT 32
#define STG 3
#define STAGE_BYTES 24576u   // Ah(0) Al(8192) B(16384), each 128x32 fp16 = 8KB

template<int MODE>
__global__ void __launch_bounds__(256, 2) gemm_hmma(
    const __half* __restrict__ Ah, const __half* __restrict__ Al, int ldA,
    const __half* __restrict__ B0, const __half* __restrict__ B1, int ldB,
    const float* __restrict__ bias0, const float* __restrict__ bias1,
    const float* __restrict__ hmul,
    float* __restrict__ fout0, float* __restrict__ fout1,
    __half* __restrict__ obh, __half* __restrict__ obl,
    int K, int nhalf, int kslices)
{
    extern __shared__ __align__(1024) char smraw[];
    const uint32_t sb = smem_u32(smraw);

    const int tid = threadIdx.x, lane = tid & 31, wid = tid >> 5;
    const int wm = (wid >> 2) * 64;
    const int wn = (wid & 3) * 32;
    const int nt = blockIdx.x, mt = blockIdx.y;
    const bool second = nt >= nhalf;
    const int ntin = second ? nt - nhalf : nt;
    const __half* Bp = second ? B1 : B0;
    const float* bias = second ? bias1 : bias0;

    const int m0 = mt * 128, n0 = ntin * 128;
    const int Ks = K / kslices;
    const int kbeg = blockIdx.z * Ks;
    const int S = Ks / KT;

    // ---- stage loader: 3 tiles of [128 rows][32 fp16] ----
    const int lr  = tid >> 1;
    const int lcb = (tid & 1) * 2;
    auto load_stage = [&](int slot, int kk) {
        const uint32_t tb = sb + (uint32_t)slot * STAGE_BYTES;
        const size_t arow = (size_t)(m0 + lr) * ldA + kk;
        const size_t brow = (size_t)(n0 + lr) * ldB + kk;
#pragma unroll
        for (int c = 0; c < 2; c++) {
            const int cb = lcb + c;
            const uint32_t sw = tb + sw_off(lr, cb);
            cp16(sw,          Ah + arow + cb * 8);
            cp16(sw + 8192,   Al + arow + cb * 8);
            cp16(sw + 16384,  Bp + brow + cb * 8);
        }
    };

    // precomputed ldsm offsets (s=0 chunk; s=1 is off ^ 32)
    const int lb = (lane >> 4) & 1;
    uint32_t offA[4], offB[2];
#pragma unroll
    for (int i = 0; i < 4; i++) offA[i] = sw_off(wm + i * 16 + (lane & 15), lb);
#pragma unroll
    for (int jp = 0; jp < 2; jp++) offB[jp] = sw_off(wn + jp * 16 + (lane & 15), lb);

    // prologue
#pragma unroll
    for (int s = 0; s < STG - 1; s++) {
        if (s < S) load_stage(s, kbeg + s * KT);
        asm volatile("cp.async.commit_group;" ::: "memory");
    }

    float acc[4][4][4];
    uint32_t accL[4][4][2];   // f16x2 accumulators for the lo term
#pragma unroll
    for (int i = 0; i < 4; i++)
#pragma unroll
        for (int j = 0; j < 4; j++) {
#pragma unroll
            for (int e = 0; e < 4; e++) acc[i][j][e] = 0.f;
            accL[i][j][0] = 0u; accL[i][j][1] = 0u;
        }

    for (int ks = 0; ks < S; ks++) {
        asm volatile("cp.async.wait_group 1;" ::: "memory");
        __syncthreads();
        if (ks + STG - 1 < S) load_stage((ks + STG - 1) % STG, kbeg + (ks + STG - 1) * KT);
        asm volatile("cp.async.commit_group;" ::: "memory");

        const uint32_t base = sb + (uint32_t)(ks % STG) * STAGE_BYTES;
#pragma unroll
        for (int s = 0; s < 2; s++) {
            const uint32_t sx = (uint32_t)(s << 5);
            uint32_t ah[4][4], b[2][4];
#pragma unroll
            for (int i = 0; i < 4; i++)   ldsm_x4(ah[i], base + (offA[i] ^ sx));
#pragma unroll
            for (int jp = 0; jp < 2; jp++) ldsm_x4(b[jp], base + 16384 + (offB[jp] ^ sx));
            // hi term: f32 accumulate
#pragma unroll
            for (int i = 0; i < 4; i++)
#pragma unroll
                for (int j = 0; j < 4; j++)
                    mma_f32(acc[i][j], ah[i], b[j >> 1][j & 1], b[j >> 1][2 | (j & 1)]);
            // prefetch Al under the MMAs
            uint32_t al[4][4];
#pragma unroll
            for (int i = 0; i < 4; i++)   ldsm_x4(al[i], base + 8192 + (offA[i] ^ sx));
            // lo term: f16 accumulate (values ~2^-11 of hi — fp16 noise negligible)
#pragma unroll
            for (int i = 0; i < 4; i++)
#pragma unroll
                for (int j = 0; j < 4; j++)
                    mma_f16(accL[i][j], al[i], b[j >> 1][j & 1], b[j >> 1][2 | (j & 1)]);
        }
    }

    // ---- epilogue: combine hi(f32) + lo(f16) ----
#pragma unroll
    for (int i = 0; i < 4; i++) {
#pragma unroll
        for (int j = 0; j < 4; j++) {
            const int r0 = m0 + wm + i * 16 + (lane >> 2);
            const int gc = ntin * 128 + wn + j * 8 + 2 * (lane & 3);
#pragma unroll
            for (int half = 0; half < 2; half++) {
                const int row = r0 + half * 8;
                const float2 lo2 = __half22float2(*(const __half2*)&accL[i][j][half]);
                const float v0r = acc[i][j][half * 2]     + lo2.x;
                const float v1r = acc[i][j][half * 2 + 1] + lo2.y;
                if (MODE == 0) {
                    const float v0 = v0r + bias[gc], v1 = v1r + bias[gc + 1];
                    if (!second) {
                        fout0[(long)row * H_ + gc]     = sigm(v0);
                        fout0[(long)row * H_ + gc + 1] = sigm(v1);
                    } else {
                        const float rh0 = sigm(v0) * hmul[(long)row * H_ + gc];
                        const float rh1 = sigm(v1) * hmul[(long)row * H_ + gc + 1];
                        __half h0, l0, h1, l1;
                        split_h(rh0, h0, l0);
                        split_h(rh1, h1, l1);
                        obh[(long)row * C_ + D_ + gc]     = h0;
                        obl[(long)row * C_ + D_ + gc]     = l0;
                        obh[(long)row * C_ + D_ + gc + 1] = h1;
                        obl[(long)row * C_ + D_ + gc + 1] = l1;
                    }
                } else if (MODE == 1) {
                    float* dst = second ? fout1 : fout0;
                    dst[(long)row * H_ + gc]     = v0r + bias[gc];
                    dst[(long)row * H_ + gc + 1] = v1r + bias[gc + 1];
                } else {
                    float* dst = fout0 + (size_t)blockIdx.z * B_ * D_;
                    dst[(long)row * D_ + gc]     = v0r;
                    dst[(long)row * D_ + gc + 1] = v1r;
                }
            }
        }
    }
}

// ---------------- conversion kernels ----------------
__global__ void conv_a1(const float* __restrict__ x, const float* __restrict__ h,
                        __half* __restrict__ a1h, __half* __restrict__ a1l,
                        __half* __restrict__ a2h, __half* __restrict__ a2l)
{
    const long i4 = (long)blockIdx.x * blockDim.x + threadIdx.x;
    if (i4 >= (long)B_ * C_ / 4) return;
    const int row = (int)(i4 / (C_ / 4));
    const int c = (int)(i4 % (C_ / 4)) * 4;
    float4 f;
    if (c < D_) f = *(const float4*)(x + (long)row * D_ + c);
    else        f = *(const float4*)(h + (long)row * H_ + (c - D_));
    __half h0, l0, h1, l1, h2, l2, h3, l3;
    split_h(f.x, h0, l0); split_h(f.y, h1, l1);
    split_h(f.z, h2, l2); split_h(f.w, h3, l3);
    __half2 hv0 = __halves2half2(h0, h1), hv1 = __halves2half2(h2, h3);
    __half2 lv0 = __halves2half2(l0, l1), lv1 = __halves2half2(l2, l3);
    const long o = (long)row * C_ + c;
    *(uint2*)(a1h + o) = make_uint2(*(uint32_t*)&hv0, *(uint32_t*)&hv1);
    *(uint2*)(a1l + o) = make_uint2(*(uint32_t*)&lv0, *(uint32_t*)&lv1);
    if (c < D_) {
        *(uint2*)(a2h + o) = make_uint2(*(uint32_t*)&hv0, *(uint32_t*)&hv1);
        *(uint2*)(a2l + o) = make_uint2(*(uint32_t*)&lv0, *(uint32_t*)&lv1);
    }
}

// batched transpose + round to fp16 for the 4 big weights
__global__ void tconv4(const float* __restrict__ s0, const float* __restrict__ s1,
                       const float* __restrict__ s2, const float* __restrict__ s3,
                       __half* __restrict__ d0, __half* __restrict__ d1,
                       __half* __restrict__ d2, __half* __restrict__ d3)
{
    const int z = blockIdx.z;
    const float* src = z == 0 ? s0 : z == 1 ? s1 : z == 2 ? s2 : s3;
    __half* dh = z == 0 ? d0 : z == 1 ? d1 : z == 2 ? d2 : d3;
    const int K = C_, N = H_;

    __shared__ float t[64][33];
    const int kt = blockIdx.y * 64, nb = blockIdx.x * 32;
    const int tid = threadIdx.x;
    {
        const int c4 = (tid & 7) * 4, r0 = tid >> 3;
#pragma unroll
        for (int p = 0; p < 2; p++) {
            const int r = r0 + p * 32;
            const float4 f = *(const float4*)(src + (size_t)(kt + r) * N + nb + c4);
            t[r][c4] = f.x; t[r][c4 + 1] = f.y; t[r][c4 + 2] = f.z; t[r][c4 + 3] = f.w;
        }
    }
    __syncthreads();
    const int n  = tid >> 3;
    const int k8 = (tid & 7) * 8;
    __half2 hv[4];
#pragma unroll
    for (int i = 0; i < 4; i++)
        hv[i] = __halves2half2(__float2half_rn(t[k8 + 2 * i][n]), __float2half_rn(t[k8 + 2 * i + 1][n]));
    const long o = (long)(nb + n) * K + kt + k8;
    *(uint4*)(dh + o) = make_uint4(*(uint32_t*)&hv[0], *(uint32_t*)&hv[1],
                                   *(uint32_t*)&hv[2], *(uint32_t*)&hv[3]);
}

__global__ void tconv(const float* __restrict__ src, __half* __restrict__ dh, int K, int N)
{
    __shared__ float t[64][33];
    const int kt = blockIdx.y * 64, nb = blockIdx.x * 32;
    const int tid = threadIdx.x;
    {
        const int c4 = (tid & 7) * 4, r0 = tid >> 3;
#pragma unroll
        for (int p = 0; p < 2; p++) {
            const int r = r0 + p * 32;
            const float4 f = *(const float4*)(src + (size_t)(kt + r) * N + nb + c4);
            t[r][c4] = f.x; t[r][c4 + 1] = f.y; t[r][c4 + 2] = f.z; t[r][c4 + 3] = f.w;
        }
    }
    __syncthreads();
    const int n  = tid >> 3;
    const int k8 = (tid & 7) * 8;
    __half2 hv[4];
#pragma unroll
    for (int i = 0; i < 4; i++)
        hv[i] = __halves2half2(__float2half_rn(t[k8 + 2 * i][n]), __float2half_rn(t[k8 + 2 * i + 1][n]));
    const long o = (long)(nb + n) * K + kt + k8;
    *(uint4*)(dh + o) = make_uint4(*(uint32_t*)&hv[0], *(uint32_t*)&hv[1],
                                   *(uint32_t*)&hv[2], *(uint32_t*)&hv[3]);
}

// ---------------- LayerNorm kernels ----------------
__global__ void ln_newh(const float* __restrict__ u, const float* __restrict__ h,
                        const float* __restrict__ g, const float* __restrict__ up,
                        const float* __restrict__ gamma, const float* __restrict__ beta,
                        float* __restrict__ out,
                        __half* __restrict__ a3h, __half* __restrict__ a3l)
{
    const int row = blockIdx.x, tid = threadIdx.x;
    const int PER = H_ / 256;
    const long base = (long)row * H_;
    float v[PER];
    float s = 0.f, ss = 0.f;
#pragma unroll
    for (int i = 0; i < PER; i++) {
        const int j = i * 256 + tid;
        const float uu = u[base + j];
        const float gg = g[base + j];
        const float val = h[base + j] * (2.f - uu) + uu * (gg * sigm(gg)) * up[base + j];
        v[i] = val; s += val; ss += val * val;
    }
    __shared__ float sm[2][8];
#pragma unroll
    for (int o = 16; o > 0; o >>= 1) {
        s  += __shfl_xor_sync(0xffffffffu, s, o);
        ss += __shfl_xor_sync(0xffffffffu, ss, o);
    }
    const int warp = tid >> 5, lane = tid & 31;
    if (lane == 0) { sm[0][warp] = s; sm[1][warp] = ss; }
    __syncthreads();
    float ts = 0.f, tss = 0.f;
#pragma unroll
    for (int w = 0; w < 8; w++) { ts += sm[0][w]; tss += sm[1][w]; }
    const float mean = ts / (float)H_;
    const float var  = tss / (float)H_ - mean * mean;
    const float rstd = rsqrtf(var + LN_EPS);
#pragma unroll
    for (int i = 0; i < PER; i++) {
        const int j = i * 256 + tid;
        const float r = (v[i] - mean) * rstd * gamma[j] + beta[j];
        out[base + j] = r;
        __half hi, lo;
        split_h(r, hi, lo);
        a3h[base + j] = hi; a3l[base + j] = lo;
    }
}

__global__ void ln_out(const float* __restrict__ in,
                       const float* __restrict__ bd,
                       const float* __restrict__ gamma, const float* __restrict__ beta,
                       float* __restrict__ out)
{
    const int row = blockIdx.x, tid = threadIdx.x;
    const int PER = D_ / 256;
    const long base = (long)row * D_;
    const long zoff = (long)B_ * D_;
    float v[PER];
    float s = 0.f, ss = 0.f;
#pragma unroll
    for (int i = 0; i < PER; i++) {
        const int j = i * 256 + tid;
        float val = bd[j];
#pragma unroll
        for (int z = 0; z < KSLICE_D; z++) val += in[z * zoff + base + j];
        v[i] = val; s += val; ss += val * val;
    }
    __shared__ float sm[2][8];
#pragma unroll
    for (int o = 16; o > 0; o >>= 1) {
        s  += __shfl_xor_sync(0xffffffffu, s, o);
        ss += __shfl_xor_sync(0xffffffffu, ss, o);
    }
    const int warp = tid >> 5, lane = tid & 31;
    if (lane == 0) { sm[0][warp] = s; sm[1][warp] = ss; }
    __syncthreads();
    float ts = 0.f, tss = 0.f;
#pragma unroll
    for (int w = 0; w < 8; w++) { ts += sm[0][w]; tss += sm[1][w]; }
    const float mean = ts / (float)D_;
    const float var  = tss / (float)D_ - mean * mean;
    const float rstd = rsqrtf(var + LN_EPS);
#pragma unroll
    for (int i = 0; i < PER; i++) {
        const int j = i * 256 + tid;
        out[base + j] = (v[i] - mean) * rstd * gamma[j] + beta[j];
    }
}

// ---------------- host ----------------
extern "C" void kernel_launch(void* const* d_in, const int* in_sizes, int n_in,
                              void* d_out, int out_size)
{
    const float* x    = (const float*)d_in[0];
    const float* h    = (const float*)d_in[1];
    const float* W_u  = (const float*)d_in[2];
    const float* b_u  = (const float*)d_in[3];
    const float* W_r  = (const float*)d_in[4];
    const float* b_r  = (const float*)d_in[5];
    const float* W_g  = (const float*)d_in[6];
    const float* b_g  = (const float*)d_in[7];
    const float* W_up = (const float*)d_in[8];
    const float* b_up = (const float*)d_in[9];
    const float* W_d  = (const float*)d_in[10];
    const float* b_d  = (const float*)d_in[11];
    const float* g_hh = (const float*)d_in[12];
    const float* be_h = (const float*)d_in[13];
    const float* g_o  = (const float*)d_in[14];
    const float* be_o = (const float*)d_in[15];
    float* out = (float*)d_out;

    void *pa1h, *pa1l, *pa2h, *pa2l, *pa3h, *pa3l;
    void *pwu, *pwr, *pwg, *pwp, *pwd;
    float *pu, *pg, *pup, *pnh, *pdo;
    cudaGetSymbolAddress(&pa1h, g_a1h); cudaGetSymbolAddress(&pa1l, g_a1l);
    cudaGetSymbolAddress(&pa2h, g_a2h); cudaGetSymbolAddress(&pa2l, g_a2l);
    cudaGetSymbolAddress(&pa3h, g_a3h); cudaGetSymbolAddress(&pa3l, g_a3l);
    cudaGetSymbolAddress(&pwu, g_wu); cudaGetSymbolAddress(&pwr, g_wr);
    cudaGetSymbolAddress(&pwg, g_wg); cudaGetSymbolAddress(&pwp, g_wp);
    cudaGetSymbolAddress(&pwd, g_wd);
    cudaGetSymbolAddress((void**)&pu,  g_u);
    cudaGetSymbolAddress((void**)&pg,  g_g);
    cudaGetSymbolAddress((void**)&pup, g_up);
    cudaGetSymbolAddress((void**)&pnh, g_nh);
    cudaGetSymbolAddress((void**)&pdo, g_do);

    constexpr int SMEM = STG * (int)STAGE_BYTES;  // 73728 -> 2 CTAs/SM
    cudaFuncSetAttribute((const void*)gemm_hmma<0>, cudaFuncAttributeMaxDynamicSharedMemorySize, SMEM);
    cudaFuncSetAttribute((const void*)gemm_hmma<1>, cudaFuncAttributeMaxDynamicSharedMemorySize, SMEM);
    cudaFuncSetAttribute((const void*)gemm_hmma<2>, cudaFuncAttributeMaxDynamicSharedMemorySize, SMEM);

    float* newh = (out_size >= B_ * (D_ + H_)) ? (out + (long)B_ * D_) : pnh;

    conv_a1<<<(unsigned)(((long)B_ * C_ / 4 + 255) / 256), 256>>>(
        x, h, (__half*)pa1h, (__half*)pa1l, (__half*)pa2h, (__half*)pa2l);

    tconv4<<<dim3(H_ / 32, C_ / 64, 4), 256>>>(
        W_u, W_r, W_g, W_up,
        (__half*)pwu, (__half*)pwr, (__half*)pwg, (__half*)pwp);
    tconv<<<dim3(D_ / 32, H_ / 64), 256>>>(W_d, (__half*)pwd, H_, D_);

    gemm_hmma<0><<<dim3(64, 8, 1), 256, SMEM>>>(
        (const __half*)pa1h, (const __half*)pa1l, C_,
        (const __half*)pwu, (const __half*)pwr, C_,
        b_u, b_r, h, pu, nullptr,
        (__half*)pa2h, (__half*)pa2l, C_, 32, 1);

    gemm_hmma<1><<<dim3(64, 8, 1), 256, SMEM>>>(
        (const __half*)pa2h, (const __half*)pa2l, C_,
        (const __half*)pwg, (const __half*)pwp, C_,
        b_g, b_up, nullptr, pg, pup, nullptr, nullptr, C_, 32, 1);

    ln_newh<<<B_, 256>>>(pu, h, pg, pup, g_hh, be_h, newh,
                         (__half*)pa3h, (__half*)pa3l);

    gemm_hmma<2><<<dim3(8, 8, KSLICE_D), 256, SMEM>>>(
        (const __half*)pa3h, (const __half*)pa3l, H_,
        (const __half*)pwd, (const __half*)pwd, H_,
        b_d, b_d, nullptr, pdo, nullptr, nullptr, nullptr, H_, 1000, KSLICE_D);

    ln_out<<<B_, 256>>>(pdo, b_d, g_o, be_o, out);
}

// round 11
// speedup vs baseline: 6.0638x; 1.7034x over previous
#include <cuda_runtime.h>
#include <cuda_fp16.h>
#include <math.h>
#include <stdint.h>

#define B_ 1024
#define D_ 1024
#define H_ 4096
#define C_ 5120
#define LN_EPS 1e-3f
#define KSLICE_D 4

// ---------------- scratch (device globals: allocation-free) ----------------
__device__ __align__(1024) __half g_a1[B_ * C_];
__device__ __align__(1024) __half g_a2[B_ * C_];
__device__ __align__(1024) __half g_a3[B_ * H_];
__device__ __align__(1024) __half g_wu[(long)H_ * C_];
__device__ __align__(1024) __half g_wr[(long)H_ * C_];
__device__ __align__(1024) __half g_wg[(long)H_ * C_];
__device__ __align__(1024) __half g_wp[(long)H_ * C_];
__device__ __align__(1024) __half g_wd[(long)D_ * H_];
__device__ float g_u [B_ * H_];
__device__ float g_g [B_ * H_];
__device__ float g_up[B_ * H_];
__device__ float g_nh[B_ * H_];
__device__ float g_do[KSLICE_D * B_ * D_];

// ---------------- helpers ----------------
__device__ __forceinline__ uint32_t smem_u32(const void* p) {
    uint32_t a;
    asm("{ .reg .u64 t; cvta.to.shared.u64 t, %1; cvt.u32.u64 %0, t; }" : "=r"(a) : "l"(p));
    return a;
}
__device__ __forceinline__ void cp16(uint32_t dst, const void* src) {
    asm volatile("cp.async.cg.shared.global [%0], [%1], 16;" :: "r"(dst), "l"(src) : "memory");
}
__device__ __forceinline__ void ldsm_x4(uint32_t* r, uint32_t addr) {
    asm volatile("ldmatrix.sync.aligned.m8n8.x4.shared.b16 {%0,%1,%2,%3}, [%4];"
                 : "=r"(r[0]), "=r"(r[1]), "=r"(r[2]), "=r"(r[3]) : "r"(addr));
}
__device__ __forceinline__ void mma_f32(float* c, const uint32_t* a, uint32_t b0, uint32_t b1) {
    asm volatile(
        "mma.sync.aligned.m16n8k16.row.col.f32.f16.f16.f32 "
        "{%0,%1,%2,%3}, {%4,%5,%6,%7}, {%8,%9}, {%0,%1,%2,%3};"
        : "+f"(c[0]), "+f"(c[1]), "+f"(c[2]), "+f"(c[3])
        : "r"(a[0]), "r"(a[1]), "r"(a[2]), "r"(a[3]), "r"(b0), "r"(b1));
}
__device__ __forceinline__ float sigm(float x) { return 1.0f / (1.0f + expf(-x)); }

// swizzled offset inside a [128 rows][32 fp16] tile (64B rows, 16B chunks)
__device__ __forceinline__ uint32_t sw_off(int row, int cb) {
    return (uint32_t)row * 64u + (uint32_t)((cb ^ ((row >> 1) & 3)) << 4);
}

// ---------------- single-term fp16 HMMA GEMM (2 CTAs/SM) ----------------
#define KT 32
#define STG 3
#define STAGE_BYTES 16384u   // A(0) B(8192), each 128x32 fp16 = 8KB

template<int MODE>
__global__ void __launch_bounds__(256, 2) gemm_hmma(
    const __half* __restrict__ A, int ldA,
    const __half* __restrict__ B0, const __half* __restrict__ B1, int ldB,
    const float* __restrict__ bias0, const float* __restrict__ bias1,
    const float* __restrict__ hmul,
    float* __restrict__ fout0, float* __restrict__ fout1,
    __half* __restrict__ oba,
    int K, int nhalf, int kslices)
{
    extern __shared__ __align__(1024) char smraw[];
    const uint32_t sb = smem_u32(smraw);

    const int tid = threadIdx.x, lane = tid & 31, wid = tid >> 5;
    const int wm = (wid >> 2) * 64;
    const int wn = (wid & 3) * 32;
    const int nt = blockIdx.x, mt = blockIdx.y;
    const bool second = nt >= nhalf;
    const int ntin = second ? nt - nhalf : nt;
    const __half* Bp = second ? B1 : B0;
    const float* bias = second ? bias1 : bias0;

    const int m0 = mt * 128, n0 = ntin * 128;
    const int Ks = K / kslices;
    const int kbeg = blockIdx.z * Ks;
    const int S = Ks / KT;

    // ---- stage loader: 2 tiles of [128 rows][32 fp16] ----
    const int lr  = tid >> 1;
    const int lcb = (tid & 1) * 2;
    auto load_stage = [&](int slot, int kk) {
        const uint32_t tb = sb + (uint32_t)slot * STAGE_BYTES;
        const size_t arow = (size_t)(m0 + lr) * ldA + kk;
        const size_t brow = (size_t)(n0 + lr) * ldB + kk;
#pragma unroll
        for (int c = 0; c < 2; c++) {
            const int cb = lcb + c;
            const uint32_t sw = tb + sw_off(lr, cb);
            cp16(sw,         A  + arow + cb * 8);
            cp16(sw + 8192,  Bp + brow + cb * 8);
        }
    };

    // precomputed ldsm offsets (s=0 chunk; s=1 is off ^ 32)
    const int lb = (lane >> 4) & 1;
    uint32_t offA[4], offB[2];
#pragma unroll
    for (int i = 0; i < 4; i++) offA[i] = sw_off(wm + i * 16 + (lane & 15), lb);
#pragma unroll
    for (int jp = 0; jp < 2; jp++) offB[jp] = sw_off(wn + jp * 16 + (lane & 15), lb);

    // prologue
#pragma unroll
    for (int s = 0; s < STG - 1; s++) {
        if (s < S) load_stage(s, kbeg + s * KT);
        asm volatile("cp.async.commit_group;" ::: "memory");
    }

    float acc[4][4][4];
#pragma unroll
    for (int i = 0; i < 4; i++)
#pragma unroll
        for (int j = 0; j < 4; j++)
#pragma unroll
            for (int e = 0; e < 4; e++) acc[i][j][e] = 0.f;

    for (int ks = 0; ks < S; ks++) {
        asm volatile("cp.async.wait_group 1;" ::: "memory");
        __syncthreads();
        if (ks + STG - 1 < S) load_stage((ks + STG - 1) % STG, kbeg + (ks + STG - 1) * KT);
        asm volatile("cp.async.commit_group;" ::: "memory");

        const uint32_t base = sb + (uint32_t)(ks % STG) * STAGE_BYTES;
#pragma unroll
        for (int s = 0; s < 2; s++) {
            const uint32_t sx = (uint32_t)(s << 5);
            uint32_t a[4][4], b[2][4];
#pragma unroll
            for (int i = 0; i < 4; i++)   ldsm_x4(a[i], base + (offA[i] ^ sx));
#pragma unroll
            for (int jp = 0; jp < 2; jp++) ldsm_x4(b[jp], base + 8192 + (offB[jp] ^ sx));
#pragma unroll
            for (int i = 0; i < 4; i++)
#pragma unroll
                for (int j = 0; j < 4; j++)
                    mma_f32(acc[i][j], a[i], b[j >> 1][j & 1], b[j >> 1][2 | (j & 1)]);
        }
    }

    // ---- epilogue ----
#pragma unroll
    for (int i = 0; i < 4; i++) {
#pragma unroll
        for (int j = 0; j < 4; j++) {
            const int r0 = m0 + wm + i * 16 + (lane >> 2);
            const int gc = ntin * 128 + wn + j * 8 + 2 * (lane & 3);
#pragma unroll
            for (int half = 0; half < 2; half++) {
                const int row = r0 + half * 8;
                const float v0r = acc[i][j][half * 2];
                const float v1r = acc[i][j][half * 2 + 1];
                if (MODE == 0) {
                    const float v0 = v0r + bias[gc], v1 = v1r + bias[gc + 1];
                    if (!second) {
                        fout0[(long)row * H_ + gc]     = sigm(v0);
                        fout0[(long)row * H_ + gc + 1] = sigm(v1);
                    } else {
                        const float rh0 = sigm(v0) * hmul[(long)row * H_ + gc];
                        const float rh1 = sigm(v1) * hmul[(long)row * H_ + gc + 1];
                        oba[(long)row * C_ + D_ + gc]     = __float2half_rn(rh0);
                        oba[(long)row * C_ + D_ + gc + 1] = __float2half_rn(rh1);
                    }
                } else if (MODE == 1) {
                    float* dst = second ? fout1 : fout0;
                    dst[(long)row * H_ + gc]     = v0r + bias[gc];
                    dst[(long)row * H_ + gc + 1] = v1r + bias[gc + 1];
                } else {
                    float* dst = fout0 + (size_t)blockIdx.z * B_ * D_;
                    dst[(long)row * D_ + gc]     = v0r;
                    dst[(long)row * D_ + gc + 1] = v1r;
                }
            }
        }
    }
}

// ---------------- conversion kernels ----------------
// A1 = fp16([x | h]); also x-part of A2
__global__ void conv_a1(const float* __restrict__ x, const float* __restrict__ h,
                        __half* __restrict__ a1, __half* __restrict__ a2)
{
    const long i4 = (long)blockIdx.x * blockDim.x + threadIdx.x;
    if (i4 >= (long)B_ * C_ / 4) return;
    const int row = (int)(i4 / (C_ / 4));
    const int c = (int)(i4 % (C_ / 4)) * 4;
    float4 f;
    if (c < D_) f = *(const float4*)(x + (long)row * D_ + c);
    else        f = *(const float4*)(h + (long)row * H_ + (c - D_));
    __half2 hv0 = __halves2half2(__float2half_rn(f.x), __float2half_rn(f.y));
    __half2 hv1 = __halves2half2(__float2half_rn(f.z), __float2half_rn(f.w));
    const long o = (long)row * C_ + c;
    *(uint2*)(a1 + o) = make_uint2(*(uint32_t*)&hv0, *(uint32_t*)&hv1);
    if (c < D_)
        *(uint2*)(a2 + o) = make_uint2(*(uint32_t*)&hv0, *(uint32_t*)&hv1);
}

// batched transpose + round to fp16 for the 4 big weights
__global__ void tconv4(const float* __restrict__ s0, const float* __restrict__ s1,
                       const float* __restrict__ s2, const float* __restrict__ s3,
                       __half* __restrict__ d0, __half* __restrict__ d1,
                       __half* __restrict__ d2, __half* __restrict__ d3)
{
    const int z = blockIdx.z;
    const float* src = z == 0 ? s0 : z == 1 ? s1 : z == 2 ? s2 : s3;
    __half* dh = z == 0 ? d0 : z == 1 ? d1 : z == 2 ? d2 : d3;
    const int K = C_, N = H_;

    __shared__ float t[64][33];
    const int kt = blockIdx.y * 64, nb = blockIdx.x * 32;
    const int tid = threadIdx.x;
    {
        const int c4 = (tid & 7) * 4, r0 = tid >> 3;
#pragma unroll
        for (int p = 0; p < 2; p++) {
            const int r = r0 + p * 32;
            const float4 f = *(const float4*)(src + (size_t)(kt + r) * N + nb + c4);
            t[r][c4] = f.x; t[r][c4 + 1] = f.y; t[r][c4 + 2] = f.z; t[r][c4 + 3] = f.w;
        }
    }
    __syncthreads();
    const int n  = tid >> 3;
    const int k8 = (tid & 7) * 8;
    __half2 hv[4];
#pragma unroll
    for (int i = 0; i < 4; i++)
        hv[i] = __halves2half2(__float2half_rn(t[k8 + 2 * i][n]), __float2half_rn(t[k8 + 2 * i + 1][n]));
    const long o = (long)(nb + n) * K + kt + k8;
    *(uint4*)(dh + o) = make_uint4(*(uint32_t*)&hv[0], *(uint32_t*)&hv[1],
                                   *(uint32_t*)&hv[2], *(uint32_t*)&hv[3]);
}

__global__ void tconv(const float* __restrict__ src, __half* __restrict__ dh, int K, int N)
{
    __shared__ float t[64][33];
    const int kt = blockIdx.y * 64, nb = blockIdx.x * 32;
    const int tid = threadIdx.x;
    {
        const int c4 = (tid & 7) * 4, r0 = tid >> 3;
#pragma unroll
        for (int p = 0; p < 2; p++) {
            const int r = r0 + p * 32;
            const float4 f = *(const float4*)(src + (size_t)(kt + r) * N + nb + c4);
            t[r][c4] = f.x; t[r][c4 + 1] = f.y; t[r][c4 + 2] = f.z; t[r][c4 + 3] = f.w;
        }
    }
    __syncthreads();
    const int n  = tid >> 3;
    const int k8 = (tid & 7) * 8;
    __half2 hv[4];
#pragma unroll
    for (int i = 0; i < 4; i++)
        hv[i] = __halves2half2(__float2half_rn(t[k8 + 2 * i][n]), __float2half_rn(t[k8 + 2 * i + 1][n]));
    const long o = (long)(nb + n) * K + kt + k8;
    *(uint4*)(dh + o) = make_uint4(*(uint32_t*)&hv[0], *(uint32_t*)&hv[1],
                                   *(uint32_t*)&hv[2], *(uint32_t*)&hv[3]);
}

// ---------------- LayerNorm kernels ----------------
__global__ void ln_newh(const float* __restrict__ u, const float* __restrict__ h,
                        const float* __restrict__ g, const float* __restrict__ up,
                        const float* __restrict__ gamma, const float* __restrict__ beta,
                        float* __restrict__ out, __half* __restrict__ a3)
{
    const int row = blockIdx.x, tid = threadIdx.x;
    const int PER = H_ / 256;
    const long base = (long)row * H_;
    float v[PER];
    float s = 0.f, ss = 0.f;
#pragma unroll
    for (int i = 0; i < PER; i++) {
        const int j = i * 256 + tid;
        const float uu = u[base + j];
        const float gg = g[base + j];
        const float val = h[base + j] * (2.f - uu) + uu * (gg * sigm(gg)) * up[base + j];
        v[i] = val; s += val; ss += val * val;
    }
    __shared__ float sm[2][8];
#pragma unroll
    for (int o = 16; o > 0; o >>= 1) {
        s  += __shfl_xor_sync(0xffffffffu, s, o);
        ss += __shfl_xor_sync(0xffffffffu, ss, o);
    }
    const int warp = tid >> 5, lane = tid & 31;
    if (lane == 0) { sm[0][warp] = s; sm[1][warp] = ss; }
    __syncthreads();
    float ts = 0.f, tss = 0.f;
#pragma unroll
    for (int w = 0; w < 8; w++) { ts += sm[0][w]; tss += sm[1][w]; }
    const float mean = ts / (float)H_;
    const float var  = tss / (float)H_ - mean * mean;
    const float rstd = rsqrtf(var + LN_EPS);
#pragma unroll
    for (int i = 0; i < PER; i++) {
        const int j = i * 256 + tid;
        const float r = (v[i] - mean) * rstd * gamma[j] + beta[j];
        out[base + j] = r;
        a3[base + j] = __float2half_rn(r);
    }
}

__global__ void ln_out(const float* __restrict__ in,
                       const float* __restrict__ bd,
                       const float* __restrict__ gamma, const float* __restrict__ beta,
                       float* __restrict__ out)
{
    const int row = blockIdx.x, tid = threadIdx.x;
    const int PER = D_ / 256;
    const long base = (long)row * D_;
    const long zoff = (long)B_ * D_;
    float v[PER];
    float s = 0.f, ss = 0.f;
#pragma unroll
    for (int i = 0; i < PER; i++) {
        const int j = i * 256 + tid;
        float val = bd[j];
#pragma unroll
        for (int z = 0; z < KSLICE_D; z++) val += in[z * zoff + base + j];
        v[i] = val; s += val; ss += val * val;
    }
    __shared__ float sm[2][8];
#pragma unroll
    for (int o = 16; o > 0; o >>= 1) {
        s  += __shfl_xor_sync(0xffffffffu, s, o);
        ss += __shfl_xor_sync(0xffffffffu, ss, o);
    }
    const int warp = tid >> 5, lane = tid & 31;
    if (lane == 0) { sm[0][warp] = s; sm[1][warp] = ss; }
    __syncthreads();
    float ts = 0.f, tss = 0.f;
#pragma unroll
    for (int w = 0; w < 8; w++) { ts += sm[0][w]; tss += sm[1][w]; }
    const float mean = ts / (float)D_;
    const float var  = tss / (float)D_ - mean * mean;
    const float rstd = rsqrtf(var + LN_EPS);
#pragma unroll
    for (int i = 0; i < PER; i++) {
        const int j = i * 256 + tid;
        out[base + j] = (v[i] - mean) * rstd * gamma[j] + beta[j];
    }
}

// ---------------- host ----------------
extern "C" void kernel_launch(void* const* d_in, const int* in_sizes, int n_in,
                              void* d_out, int out_size)
{
    const float* x    = (const float*)d_in[0];
    const float* h    = (const float*)d_in[1];
    const float* W_u  = (const float*)d_in[2];
    const float* b_u  = (const float*)d_in[3];
    const float* W_r  = (const float*)d_in[4];
    const float* b_r  = (const float*)d_in[5];
    const float* W_g  = (const float*)d_in[6];
    const float* b_g  = (const float*)d_in[7];
    const float* W_up = (const float*)d_in[8];
    const float* b_up = (const float*)d_in[9];
    const float* W_d  = (const float*)d_in[10];
    const float* b_d  = (const float*)d_in[11];
    const float* g_hh = (const float*)d_in[12];
    const float* be_h = (const float*)d_in[13];
    const float* g_o  = (const float*)d_in[14];
    const float* be_o = (const float*)d_in[15];
    float* out = (float*)d_out;

    void *pa1, *pa2, *pa3, *pwu, *pwr, *pwg, *pwp, *pwd;
    float *pu, *pg, *pup, *pnh, *pdo;
    cudaGetSymbolAddress(&pa1, g_a1);
    cudaGetSymbolAddress(&pa2, g_a2);
    cudaGetSymbolAddress(&pa3, g_a3);
    cudaGetSymbolAddress(&pwu, g_wu); cudaGetSymbolAddress(&pwr, g_wr);
    cudaGetSymbolAddress(&pwg, g_wg); cudaGetSymbolAddress(&pwp, g_wp);
    cudaGetSymbolAddress(&pwd, g_wd);
    cudaGetSymbolAddress((void**)&pu,  g_u);
    cudaGetSymbolAddress((void**)&pg,  g_g);
    cudaGetSymbolAddress((void**)&pup, g_up);
    cudaGetSymbolAddress((void**)&pnh, g_nh);
    cudaGetSymbolAddress((void**)&pdo, g_do);

    constexpr int SMEM = STG * (int)STAGE_BYTES;  // 49152 -> 2 CTAs/SM
    cudaFuncSetAttribute((const void*)gemm_hmma<0>, cudaFuncAttributeMaxDynamicSharedMemorySize, SMEM);
    cudaFuncSetAttribute((const void*)gemm_hmma<1>, cudaFuncAttributeMaxDynamicSharedMemorySize, SMEM);
    cudaFuncSetAttribute((const void*)gemm_hmma<2>, cudaFuncAttributeMaxDynamicSharedMemorySize, SMEM);

    float* newh = (out_size >= B_ * (D_ + H_)) ? (out + (long)B_ * D_) : pnh;

    conv_a1<<<(unsigned)(((long)B_ * C_ / 4 + 255) / 256), 256>>>(
        x, h, (__half*)pa1, (__half*)pa2);

    tconv4<<<dim3(H_ / 32, C_ / 64, 4), 256>>>(
        W_u, W_r, W_g, W_up,
        (__half*)pwu, (__half*)pwr, (__half*)pwg, (__half*)pwp);
    tconv<<<dim3(D_ / 32, H_ / 64), 256>>>(W_d, (__half*)pwd, H_, D_);

    // u = sigmoid([x|h]Wu+bu);  rh = sigmoid([x|h]Wr+br)*h -> fp16 into A2
    gemm_hmma<0><<<dim3(64, 8, 1), 256, SMEM>>>(
        (const __half*)pa1, C_,
        (const __half*)pwu, (const __half*)pwr, C_,
        b_u, b_r, h, pu, nullptr,
        (__half*)pa2, C_, 32, 1);

    // g = [x|rh]Wg+bg ; up = [x|rh]Wup+bup (raw f32)
    gemm_hmma<1><<<dim3(64, 8, 1), 256, SMEM>>>(
        (const __half*)pa2, C_,
        (const __half*)pwg, (const __half*)pwp, C_,
        b_g, b_up, nullptr, pg, pup, nullptr, C_, 32, 1);

    ln_newh<<<B_, 256>>>(pu, h, pg, pup, g_hh, be_h, newh, (__half*)pa3);

    // down: new_h @ W_d (split-K x4, raw partials)
    gemm_hmma<2><<<dim3(8, 8, KSLICE_D), 256, SMEM>>>(
        (const __half*)pa3, H_,
        (const __half*)pwd, (const __half*)pwd, H_,
        b_d, b_d, nullptr, pdo, nullptr, nullptr, H_, 1000, KSLICE_D);

    ln_out<<<B_, 256>>>(pdo, b_d, g_o, be_o, out);
}